// round 1
// baseline (speedup 1.0000x reference)
#include <cuda_runtime.h>

#define NB 8
#define C1 256
#define C2 512
#define HW 4096
#define D  64
#define M  1024

// Scratch (device globals: allocation-free rule)
__device__ float g_x2p[NB * C2 * M];   // [b][c][m]  16 MB
__device__ float g_Q[NB * HW * D];     // [b][n][d]   8 MB
__device__ float g_K[NB * M * D];      // [b][m][d]   2 MB
__device__ float g_Vt[NB * D * M];     // [b][d][m]   2 MB

__device__ __forceinline__ void dot4acc(float acc[4][4], const float4 a[4], const float4 b[4]) {
#pragma unroll
    for (int i = 0; i < 4; i++)
#pragma unroll
        for (int j = 0; j < 4; j++) {
            acc[i][j] = fmaf(a[i].x, b[j].x, acc[i][j]);
            acc[i][j] = fmaf(a[i].y, b[j].y, acc[i][j]);
            acc[i][j] = fmaf(a[i].z, b[j].z, acc[i][j]);
            acc[i][j] = fmaf(a[i].w, b[j].w, acc[i][j]);
        }
}

__device__ __forceinline__ void opacc(float acc[4][4], float4 a, float4 b) {
    float av[4] = {a.x, a.y, a.z, a.w};
    float bv[4] = {b.x, b.y, b.z, b.w};
#pragma unroll
    for (int i = 0; i < 4; i++)
#pragma unroll
        for (int j = 0; j < 4; j++)
            acc[i][j] = fmaf(av[i], bv[j], acc[i][j]);
}

// ---------------- kernel 0: 2x2 average pool  x2 -> g_x2p ----------------
__global__ void pool_kernel(const float* __restrict__ x2) {
    int i  = blockIdx.x * 256 + threadIdx.x;      // < NB*C2*M = 4194304
    int m  = i & (M - 1);
    int bc = i >> 10;                             // b*C2 + c
    int h2 = m >> 5, w2 = m & 31;
    const float* s = x2 + (size_t)bc * 4096 + (h2 << 7) + (w2 << 1);
    g_x2p[i] = 0.25f * (s[0] + s[1] + s[64] + s[65]);
}

// ---------------- kernel 1: K/V projection ----------------
// K[b,m,d] = sum_c x2p[b,c,m]*Wk[d,c] + bk[d]   -> g_K  [b][m][d]
// V likewise, stored transposed                  -> g_Vt [b][d][m]
__global__ __launch_bounds__(256) void kv_kernel(
        const float* __restrict__ Wk, const float* __restrict__ bk,
        const float* __restrict__ Wv, const float* __restrict__ bv) {
    __shared__ float sX[32 * 64], sWk[32 * 64], sWv[32 * 64];
    int b = blockIdx.y, m0 = blockIdx.x << 6;
    int tid = threadIdx.x, tx = tid & 15, ty = tid >> 4;
    float aK[4][4] = {}, aV[4][4] = {};

    for (int cc = 0; cc < C2; cc += 32) {
        __syncthreads();
        for (int i = tid; i < 2048; i += 256) {
            int c = i >> 6, mm = i & 63;
            sX[i] = g_x2p[((b * C2 + cc + c) << 10) + m0 + mm];
        }
        for (int i = tid; i < 2048; i += 256) {
            int c = i & 31, d = i >> 5;
            int ad = (c << 6) + ((((d >> 2) ^ (c & 7)) << 2) | (d & 3));
            sWk[ad] = Wk[d * C2 + cc + c];
            sWv[ad] = Wv[d * C2 + cc + c];
        }
        __syncthreads();
#pragma unroll
        for (int c = 0; c < 32; c++) {
            float4 xm = *(const float4*)&sX[(c << 6) + (ty << 2)];
            int col = (c << 6) + ((tx ^ (c & 7)) << 2);
            float4 wk = *(const float4*)&sWk[col];
            float4 wv = *(const float4*)&sWv[col];
            opacc(aK, xm, wk);
            opacc(aV, xm, wv);
        }
    }
    float bkv[4], bvv[4];
#pragma unroll
    for (int j = 0; j < 4; j++) { bkv[j] = bk[(tx << 2) + j]; bvv[j] = bv[(tx << 2) + j]; }
#pragma unroll
    for (int i = 0; i < 4; i++) {
        float4 o = make_float4(aK[i][0] + bkv[0], aK[i][1] + bkv[1],
                               aK[i][2] + bkv[2], aK[i][3] + bkv[3]);
        *(float4*)&g_K[(size_t)((b << 10) + m0 + (ty << 2) + i) * 64 + (tx << 2)] = o;
    }
#pragma unroll
    for (int j = 0; j < 4; j++) {
        float4 o = make_float4(aV[0][j] + bvv[j], aV[1][j] + bvv[j],
                               aV[2][j] + bvv[j], aV[3][j] + bvv[j]);
        *(float4*)&g_Vt[(size_t)((b << 6) + (tx << 2) + j) * M + m0 + (ty << 2)] = o;
    }
}

// ---------------- kernel 2: Q projection ----------------
// Q[b,n,d] = sum_c x1[b,c,n]*Wq[d,c] + bq[d]  -> g_Q [b][n][d]
__global__ __launch_bounds__(256) void q_kernel(
        const float* __restrict__ x1, const float* __restrict__ Wq,
        const float* __restrict__ bq) {
    __shared__ float sX[32 * 64], sW[32 * 64];
    int b = blockIdx.y, n0 = blockIdx.x << 6;
    int tid = threadIdx.x, tx = tid & 15, ty = tid >> 4;
    float aQ[4][4] = {};

    for (int cc = 0; cc < C1; cc += 32) {
        __syncthreads();
        for (int i = tid; i < 2048; i += 256) {
            int c = i >> 6, nn = i & 63;
            sX[i] = x1[((size_t)(b * C1 + cc + c) << 12) + n0 + nn];
        }
        for (int i = tid; i < 2048; i += 256) {
            int c = i & 31, d = i >> 5;
            int ad = (c << 6) + ((((d >> 2) ^ (c & 7)) << 2) | (d & 3));
            sW[ad] = Wq[d * C1 + cc + c];
        }
        __syncthreads();
#pragma unroll
        for (int c = 0; c < 32; c++) {
            float4 xm = *(const float4*)&sX[(c << 6) + (ty << 2)];
            float4 wq = *(const float4*)&sW[(c << 6) + ((tx ^ (c & 7)) << 2)];
            opacc(aQ, xm, wq);
        }
    }
    float bqv[4];
#pragma unroll
    for (int j = 0; j < 4; j++) bqv[j] = bq[(tx << 2) + j];
#pragma unroll
    for (int i = 0; i < 4; i++) {
        float4 o = make_float4(aQ[i][0] + bqv[0], aQ[i][1] + bqv[1],
                               aQ[i][2] + bqv[2], aQ[i][3] + bqv[3]);
        *(float4*)&g_Q[(size_t)((b << 12) + n0 + (ty << 2) + i) * 64 + (tx << 2)] = o;
    }
}

// ---------------- kernel 3: fused attention + out-proj + residual ----------------
// Per block: batch b, 64 queries. Flash-style over 16 key tiles of 64.
// Smem (dynamic 128 KB):
//   [0     , 4096 ) sQ [q][d]            (reused as sO after attention)
//   [4096  , 8192 ) sK [k][d] swizzled   (reused as sY 64*65 after attention)
//   [8192  , 12288) sV [d][k] swizzled
//   [12288 , 16384) sP [q][k] swizzled
//   [16384 , 32768) sWo [c][d] swizzled
__global__ __launch_bounds__(256, 1) void attn_kernel(
        const float* __restrict__ x1, const float* __restrict__ Wo,
        const float* __restrict__ bo, float* __restrict__ out) {
    extern __shared__ float sm[];
    float* sQ  = sm;
    float* sK  = sm + 4096;
    float* sV  = sm + 8192;
    float* sP  = sm + 12288;
    float* sO  = sm;            // alias of sQ
    float* sY  = sm + 4096;     // alias of sK (+64 floats into sV, both dead)
    float* sWo = sm + 16384;

    int b = blockIdx.y, n0 = blockIdx.x << 6;
    int tid = threadIdx.x, tx = tid & 15, ty = tid >> 4;

    // Wo [256][64] swizzled: phys f4col = (d>>2) ^ ((c>>2)&7)
    for (int i = tid; i < C1 * D; i += 256) {
        int c = i >> 6, d = i & 63;
        sWo[(c << 6) + ((((d >> 2) ^ ((c >> 2) & 7)) << 2) | (d & 3))] = Wo[i];
    }
    // Q tile, natural [q][d]
    const float* Qg = g_Q + ((size_t)(b << 12) + n0) * D;
    for (int i = tid; i < 4096; i += 256) sQ[i] = Qg[i];

    float rO[4][4] = {};
    float l[4] = {};

    for (int kt = 0; kt < M / 64; kt++) {
        __syncthreads();
        const float* Kg = g_K + ((size_t)(b << 10) + (kt << 6)) * D;
        for (int i = tid; i < 4096; i += 256) {
            int k = i >> 6, d = i & 63;
            sK[(k << 6) + ((((d >> 2) ^ ((k >> 2) & 7)) << 2) | (d & 3))] = Kg[i];
        }
        const float* Vg = g_Vt + (size_t)b * D * M + (kt << 6);
        for (int i = tid; i < 4096; i += 256) {
            int d = i >> 6, k = i & 63;
            sV[(d << 6) + ((((k >> 2) ^ ((d >> 2) & 7)) << 2) | (k & 3))] = Vg[(d << 10) + k];
        }
        __syncthreads();

        // GEMM1: S[i][j] = sum_d Q[4ty+i][d] * K[4tx+j][d]
        float S[4][4] = {};
        {
            const float* qb = sQ + (ty << 8);
            const float* kb = sK + (tx << 8);
            int ks = (tx & 7) << 2;
#pragma unroll
            for (int d = 0; d < 64; d += 4) {
                float4 a[4], bb[4];
#pragma unroll
                for (int i = 0; i < 4; i++) a[i] = *(const float4*)&qb[(i << 6) + d];
                int col = d ^ ks;
#pragma unroll
                for (int j = 0; j < 4; j++) bb[j] = *(const float4*)&kb[(j << 6) + col];
                dot4acc(S, a, bb);
            }
        }
        // softmax numerator (logits bounded, no max-subtraction needed) + row sums
        int pcol = (tx ^ (ty & 7)) << 2;
#pragma unroll
        for (int i = 0; i < 4; i++) {
            float4 p;
            p.x = __expf(S[i][0]); p.y = __expf(S[i][1]);
            p.z = __expf(S[i][2]); p.w = __expf(S[i][3]);
            float s = p.x + p.y + p.z + p.w;
            s += __shfl_xor_sync(0xffffffffu, s, 1);
            s += __shfl_xor_sync(0xffffffffu, s, 2);
            s += __shfl_xor_sync(0xffffffffu, s, 4);
            s += __shfl_xor_sync(0xffffffffu, s, 8);
            l[i] += s;
            *(float4*)&sP[(ty << 8) + (i << 6) + pcol] = p;
        }
        __syncthreads();

        // GEMM2: rO[i][j] += sum_k P[4ty+i][k] * V[k][4tx+j]  (V stored [d][k])
        {
            const float* pb = sP + (ty << 8);
            const float* vb = sV + (tx << 8);
            int ps = (ty & 7) << 2, vs = (tx & 7) << 2;
#pragma unroll
            for (int k = 0; k < 64; k += 4) {
                float4 a[4], bb[4];
                int pc = k ^ ps, vc = k ^ vs;
#pragma unroll
                for (int i = 0; i < 4; i++) a[i] = *(const float4*)&pb[(i << 6) + pc];
#pragma unroll
                for (int j = 0; j < 4; j++) bb[j] = *(const float4*)&vb[(j << 6) + vc];
                dot4acc(rO, a, bb);
            }
        }
    }

    // normalize, stage O -> smem [q][d] (unswizzled; reads below are broadcast)
#pragma unroll
    for (int i = 0; i < 4; i++) {
        float inv = 1.0f / l[i];
        *(float4*)&sO[(ty << 8) + (i << 6) + (tx << 2)] =
            make_float4(rO[i][0] * inv, rO[i][1] * inv, rO[i][2] * inv, rO[i][3] * inv);
    }
    __syncthreads();

    // GEMM3 + bias + residual, 4 chunks of 64 output channels
    const size_t xoff = (size_t)b * (C1 * HW) + n0;
    for (int cc = 0; cc < 4; cc++) {
        float Y[4][4] = {};
        {
            const float* ob = sO + (ty << 8);
            const float* wb = sWo + (cc << 12) + (tx << 8);
            int ws = (tx & 7) << 2;
#pragma unroll
            for (int d = 0; d < 64; d += 4) {
                float4 a[4], bb[4];
#pragma unroll
                for (int i = 0; i < 4; i++) a[i] = *(const float4*)&ob[(i << 6) + d];
                int wc = d ^ ws;
#pragma unroll
                for (int j = 0; j < 4; j++) bb[j] = *(const float4*)&wb[(j << 6) + wc];
                dot4acc(Y, a, bb);
            }
        }
        __syncthreads();   // previous chunk's sY fully consumed
#pragma unroll
        for (int j = 0; j < 4; j++) {
            float boj = bo[(cc << 6) + (tx << 2) + j];
#pragma unroll
            for (int i = 0; i < 4; i++)
                sY[((tx << 2) + j) * 65 + (ty << 2) + i] = Y[i][j] + boj;
        }
        __syncthreads();
        for (int i2 = tid; i2 < 4096; i2 += 256) {
            int cl = i2 >> 6, q = i2 & 63;
            size_t g = xoff + (size_t)((cc << 6) + cl) * HW + q;
            out[g] = x1[g] + sY[cl * 65 + q];
        }
    }
}

extern "C" void kernel_launch(void* const* d_in, const int* in_sizes, int n_in,
                              void* d_out, int out_size) {
    const float* x1 = (const float*)d_in[0];
    const float* x2 = (const float*)d_in[1];
    const float* Wq = (const float*)d_in[2];
    const float* bq = (const float*)d_in[3];
    const float* Wk = (const float*)d_in[4];
    const float* bk = (const float*)d_in[5];
    const float* Wv = (const float*)d_in[6];
    const float* bv = (const float*)d_in[7];
    const float* Wo = (const float*)d_in[8];
    const float* bo = (const float*)d_in[9];
    float* out = (float*)d_out;
    (void)in_sizes; (void)n_in; (void)out_size; (void)bq;

    cudaFuncSetAttribute(attn_kernel, cudaFuncAttributeMaxDynamicSharedMemorySize,
                         32768 * sizeof(float));

    pool_kernel<<<(NB * C2 * M) / 256, 256>>>(x2);
    kv_kernel<<<dim3(M / 64, NB), 256>>>(Wk, bk, Wv, bv);
    q_kernel<<<dim3(HW / 64, NB), 256>>>(x1, Wq, bq);
    attn_kernel<<<dim3(HW / 64, NB), 256, 32768 * sizeof(float)>>>(x1, Wo, bo, out);
}

// round 2
// speedup vs baseline: 3.1351x; 3.1351x over previous
#include <cuda_runtime.h>
#include <cuda_bf16.h>
#include <cstdint>

#define NB 8
#define C1 256
#define C2 512
#define HW 4096
#define D  64
#define M  1024
#define LDY 132

// Scratch (device globals: allocation-free rule)
__device__ float         g_x2p[NB * C2 * M];   // [b][c][m] fp32, 16 MB
__device__ __nv_bfloat16 g_Qh[NB * HW * D];    // [b][n][d]  4 MB
__device__ __nv_bfloat16 g_Kh[NB * M * D];     // [b][m][d]  1 MB
__device__ __nv_bfloat16 g_Vth[NB * D * M];    // [b][d][m]  1 MB (V transposed)

__device__ __forceinline__ uint32_t pack_bf16(float a, float b) {
    __nv_bfloat162 h = __floats2bfloat162_rn(a, b);
    return *reinterpret_cast<uint32_t*>(&h);
}

__device__ __forceinline__ void ldsm4(uint32_t& r0, uint32_t& r1, uint32_t& r2,
                                      uint32_t& r3, uint32_t addr) {
    asm volatile("ldmatrix.sync.aligned.m8n8.x4.shared.b16 {%0,%1,%2,%3}, [%4];\n"
                 : "=r"(r0), "=r"(r1), "=r"(r2), "=r"(r3) : "r"(addr));
}

__device__ __forceinline__ void mma16816(float c[4], const uint32_t a[4],
                                         uint32_t b0, uint32_t b1) {
    asm volatile("mma.sync.aligned.m16n8k16.row.col.f32.bf16.bf16.f32 "
                 "{%0,%1,%2,%3}, {%4,%5,%6,%7}, {%8,%9}, {%0,%1,%2,%3};\n"
                 : "+f"(c[0]), "+f"(c[1]), "+f"(c[2]), "+f"(c[3])
                 : "r"(a[0]), "r"(a[1]), "r"(a[2]), "r"(a[3]), "r"(b0), "r"(b1));
}

__device__ __forceinline__ void opacc(float acc[4][4], float4 a, float4 b) {
    float av[4] = {a.x, a.y, a.z, a.w};
    float bv[4] = {b.x, b.y, b.z, b.w};
#pragma unroll
    for (int i = 0; i < 4; i++)
#pragma unroll
        for (int j = 0; j < 4; j++)
            acc[i][j] = fmaf(av[i], bv[j], acc[i][j]);
}

// ---------------- kernel 0: 2x2 average pool ----------------
__global__ void pool_kernel(const float* __restrict__ x2) {
    int i  = blockIdx.x * 256 + threadIdx.x;
    int m  = i & (M - 1);
    int bc = i >> 10;
    int h2 = m >> 5, w2 = m & 31;
    const float* s = x2 + (size_t)bc * 4096 + (h2 << 7) + (w2 << 1);
    g_x2p[i] = 0.25f * (s[0] + s[1] + s[64] + s[65]);
}

// ---------------- kernel 1: K/V projection (fp32 math, bf16 out) ----------------
__global__ __launch_bounds__(256) void kv_kernel(
        const float* __restrict__ Wk, const float* __restrict__ bk,
        const float* __restrict__ Wv, const float* __restrict__ bv) {
    __shared__ float sX[32 * 64], sWk[32 * 64], sWv[32 * 64];
    int b = blockIdx.y, m0 = blockIdx.x << 6;
    int tid = threadIdx.x, tx = tid & 15, ty = tid >> 4;
    float aK[4][4] = {}, aV[4][4] = {};

    for (int cc = 0; cc < C2; cc += 32) {
        __syncthreads();
        for (int i = tid; i < 2048; i += 256) {
            int c = i >> 6, mm = i & 63;
            sX[i] = g_x2p[((b * C2 + cc + c) << 10) + m0 + mm];
        }
        for (int i = tid; i < 2048; i += 256) {
            int c = i & 31, d = i >> 5;
            int ad = (c << 6) + ((((d >> 2) ^ (c & 7)) << 2) | (d & 3));
            sWk[ad] = Wk[d * C2 + cc + c];
            sWv[ad] = Wv[d * C2 + cc + c];
        }
        __syncthreads();
#pragma unroll
        for (int c = 0; c < 32; c++) {
            float4 xm = *(const float4*)&sX[(c << 6) + (ty << 2)];
            int col = (c << 6) + ((tx ^ (c & 7)) << 2);
            float4 wk = *(const float4*)&sWk[col];
            float4 wv = *(const float4*)&sWv[col];
            opacc(aK, xm, wk);
            opacc(aV, xm, wv);
        }
    }
    float bkv[4], bvv[4];
#pragma unroll
    for (int j = 0; j < 4; j++) { bkv[j] = bk[(tx << 2) + j]; bvv[j] = bv[(tx << 2) + j]; }
#pragma unroll
    for (int i = 0; i < 4; i++) {
        uint2 pk;
        pk.x = pack_bf16(aK[i][0] + bkv[0], aK[i][1] + bkv[1]);
        pk.y = pack_bf16(aK[i][2] + bkv[2], aK[i][3] + bkv[3]);
        *(uint2*)&g_Kh[(size_t)((b << 10) + m0 + (ty << 2) + i) * 64 + (tx << 2)] = pk;
    }
#pragma unroll
    for (int j = 0; j < 4; j++) {
        uint2 pk;
        pk.x = pack_bf16(aV[0][j] + bvv[j], aV[1][j] + bvv[j]);
        pk.y = pack_bf16(aV[2][j] + bvv[j], aV[3][j] + bvv[j]);
        *(uint2*)&g_Vth[(size_t)((b << 6) + (tx << 2) + j) * M + m0 + (ty << 2)] = pk;
    }
}

// ---------------- kernel 2: Q projection (fp32 math, bf16 out) ----------------
__global__ __launch_bounds__(256) void q_kernel(
        const float* __restrict__ x1, const float* __restrict__ Wq,
        const float* __restrict__ bq) {
    __shared__ float sX[32 * 64], sW[32 * 64];
    int b = blockIdx.y, n0 = blockIdx.x << 6;
    int tid = threadIdx.x, tx = tid & 15, ty = tid >> 4;
    float aQ[4][4] = {};

    for (int cc = 0; cc < C1; cc += 32) {
        __syncthreads();
        for (int i = tid; i < 2048; i += 256) {
            int c = i >> 6, nn = i & 63;
            sX[i] = x1[((size_t)(b * C1 + cc + c) << 12) + n0 + nn];
        }
        for (int i = tid; i < 2048; i += 256) {
            int c = i & 31, d = i >> 5;
            int ad = (c << 6) + ((((d >> 2) ^ (c & 7)) << 2) | (d & 3));
            sW[ad] = Wq[d * C1 + cc + c];
        }
        __syncthreads();
#pragma unroll
        for (int c = 0; c < 32; c++) {
            float4 xm = *(const float4*)&sX[(c << 6) + (ty << 2)];
            float4 wq = *(const float4*)&sW[(c << 6) + ((tx ^ (c & 7)) << 2)];
            opacc(aQ, xm, wq);
        }
    }
    float bqv[4];
#pragma unroll
    for (int j = 0; j < 4; j++) bqv[j] = bq[(tx << 2) + j];
#pragma unroll
    for (int i = 0; i < 4; i++) {
        uint2 pk;
        pk.x = pack_bf16(aQ[i][0] + bqv[0], aQ[i][1] + bqv[1]);
        pk.y = pack_bf16(aQ[i][2] + bqv[2], aQ[i][3] + bqv[3]);
        *(uint2*)&g_Qh[(size_t)((b << 12) + n0 + (ty << 2) + i) * 64 + (tx << 2)] = pk;
    }
}

// ---------------- kernel 3: tensor-core attention + out-proj + residual ----------------
// CTA: 128 queries, 8 warps (warp = 16 q, all keys). Keys processed in 16 tiles of 64.
// Smem (bytes):
//   phase A: sQ [0,16384)  sK [16384,24576)  sV [24576,32768)   (bf16, XOR-swizzled)
//   phase B: sWo [0,32768) bf16 swizzled;  sY fp32 [32768, 32768+64*132*4)
__global__ __launch_bounds__(256, 2) void attn_kernel(
        const float* __restrict__ x1, const float* __restrict__ Wo,
        const float* __restrict__ bo, float* __restrict__ out) {
    extern __shared__ char sm[];
    char* sQ = sm;
    char* sK = sm + 16384;
    char* sV = sm + 24576;
    char* sWo = sm;
    float* sY = (float*)(sm + 32768);

    const int b = blockIdx.y, n0 = blockIdx.x << 7;
    const int tid = threadIdx.x, wid = tid >> 5, lane = tid & 31;
    const uint32_t sQ_u = (uint32_t)__cvta_generic_to_shared(sQ);
    const uint32_t sK_u = (uint32_t)__cvta_generic_to_shared(sK);
    const uint32_t sV_u = (uint32_t)__cvta_generic_to_shared(sV);
    const uint32_t sWo_u = (uint32_t)__cvta_generic_to_shared(sWo);

    const __nv_bfloat16* Qg = g_Qh + ((size_t)b * HW + n0) * 64;
    const __nv_bfloat16* Kg0 = g_Kh + (size_t)b * M * 64;
    const __nv_bfloat16* Vg0 = g_Vth + (size_t)b * 64 * M;

    // ---- load Q tile (128x64 bf16, swizzled) ----
    for (int i = tid; i < 1024; i += 256) {
        int r = i >> 3, g = i & 7;
        uint4 v = *(const uint4*)(Qg + r * 64 + g * 8);
        *(uint4*)(sQ + r * 128 + (((g ^ (r & 7))) << 4)) = v;
    }
    // ---- load K/V tile 0 ----
    {
        const __nv_bfloat16* Kg = Kg0;
        const __nv_bfloat16* Vg = Vg0;
        for (int i = tid; i < 512; i += 256) {
            int r = i >> 3, g = i & 7;
            uint4 v = *(const uint4*)(Kg + r * 64 + g * 8);
            *(uint4*)(sK + r * 128 + ((g ^ (r & 7)) << 4)) = v;
            uint4 w = *(const uint4*)(Vg + r * M + g * 8);
            *(uint4*)(sV + r * 128 + ((g ^ (r & 7)) << 4)) = w;
        }
    }
    __syncthreads();

    // ---- Q fragments: 4 k-steps of m16k16, held for the whole kernel ----
    uint32_t Qf[4][4];
    {
        int qr = (wid << 4) + (lane & 15);
        int roff = qr * 128, r7 = qr & 7;
#pragma unroll
        for (int s = 0; s < 4; s++) {
            int g = (s << 1) + (lane >> 4);
            ldsm4(Qf[s][0], Qf[s][1], Qf[s][2], Qf[s][3],
                  sQ_u + roff + ((g ^ r7) << 4));
        }
    }

    float O[8][4] = {};
    float l0 = 0.f, l1 = 0.f;

    // per-lane ldmatrix addressing pieces for B-operands (K/V/Wo share the pattern)
    const int brow = (lane & 7) + ((lane >> 4) << 3);   // row within 16-row group
    const int bgsel = (lane >> 3) & 1;                  // k-granule select

    for (int kt = 0; kt < 16; kt++) {
        // ---- S = Q K^T over this 64-key tile ----
        float S[8][4] = {};
#pragma unroll
        for (int s = 0; s < 4; s++) {
#pragma unroll
            for (int nh = 0; nh < 4; nh++) {
                int r = (nh << 4) + brow;
                int g = (s << 1) + bgsel;
                uint32_t b0, b1, b2, b3;
                ldsm4(b0, b1, b2, b3, sK_u + r * 128 + ((g ^ (r & 7)) << 4));
                mma16816(S[2 * nh], Qf[s], b0, b1);
                mma16816(S[2 * nh + 1], Qf[s], b2, b3);
            }
        }
        // ---- softmax numerator (no max-subtraction; |S| small) ----
        uint32_t Pf[4][4];
#pragma unroll
        for (int nt = 0; nt < 8; nt++) {
#pragma unroll
            for (int j = 0; j < 4; j++) S[nt][j] = __expf(S[nt][j]);
            l0 += S[nt][0] + S[nt][1];
            l1 += S[nt][2] + S[nt][3];
        }
#pragma unroll
        for (int kk = 0; kk < 4; kk++) {
            Pf[kk][0] = pack_bf16(S[2 * kk][0], S[2 * kk][1]);
            Pf[kk][1] = pack_bf16(S[2 * kk][2], S[2 * kk][3]);
            Pf[kk][2] = pack_bf16(S[2 * kk + 1][0], S[2 * kk + 1][1]);
            Pf[kk][3] = pack_bf16(S[2 * kk + 1][2], S[2 * kk + 1][3]);
        }
        // ---- O += P V ----
#pragma unroll
        for (int kk = 0; kk < 4; kk++) {
#pragma unroll
            for (int dh = 0; dh < 4; dh++) {
                int r = (dh << 4) + brow;
                int g = (kk << 1) + bgsel;
                uint32_t b0, b1, b2, b3;
                ldsm4(b0, b1, b2, b3, sV_u + r * 128 + ((g ^ (r & 7)) << 4));
                mma16816(O[2 * dh], Pf[kk], b0, b1);
                mma16816(O[2 * dh + 1], Pf[kk], b2, b3);
            }
        }
        // ---- prefetch next K/V tile ----
        if (kt < 15) {
            __syncthreads();
            const __nv_bfloat16* Kg = Kg0 + (kt + 1) * 64 * 64;
            const __nv_bfloat16* Vg = Vg0 + (kt + 1) * 64;
            for (int i = tid; i < 512; i += 256) {
                int r = i >> 3, g = i & 7;
                uint4 v = *(const uint4*)(Kg + r * 64 + g * 8);
                *(uint4*)(sK + r * 128 + ((g ^ (r & 7)) << 4)) = v;
                uint4 w = *(const uint4*)(Vg + r * M + g * 8);
                *(uint4*)(sV + r * 128 + ((g ^ (r & 7)) << 4)) = w;
            }
            __syncthreads();
        }
    }

    // ---- normalize, build O fragments (A-operand for out-proj) ----
    l0 += __shfl_xor_sync(0xffffffffu, l0, 1);
    l0 += __shfl_xor_sync(0xffffffffu, l0, 2);
    l1 += __shfl_xor_sync(0xffffffffu, l1, 1);
    l1 += __shfl_xor_sync(0xffffffffu, l1, 2);
    float inv0 = 1.0f / l0, inv1 = 1.0f / l1;
    uint32_t Of[4][4];
#pragma unroll
    for (int s = 0; s < 4; s++) {
        Of[s][0] = pack_bf16(O[2 * s][0] * inv0, O[2 * s][1] * inv0);
        Of[s][1] = pack_bf16(O[2 * s][2] * inv1, O[2 * s][3] * inv1);
        Of[s][2] = pack_bf16(O[2 * s + 1][0] * inv0, O[2 * s + 1][1] * inv0);
        Of[s][3] = pack_bf16(O[2 * s + 1][2] * inv1, O[2 * s + 1][3] * inv1);
    }

    // ---- phase B: load Wo (fp32 -> bf16, swizzled) ----
    __syncthreads();
    for (int i = tid; i < 2048; i += 256) {
        int c = i >> 3, g = i & 7;
        const float4* wp = (const float4*)(Wo + c * 64 + g * 8);
        float4 w0 = wp[0], w1 = wp[1];
        uint4 v;
        v.x = pack_bf16(w0.x, w0.y);
        v.y = pack_bf16(w0.z, w0.w);
        v.z = pack_bf16(w1.x, w1.y);
        v.w = pack_bf16(w1.z, w1.w);
        *(uint4*)(sWo + c * 128 + ((g ^ (c & 7)) << 4)) = v;
    }
    __syncthreads();

    // ---- out-proj + bias + residual, 4 chunks of 64 channels ----
    const size_t xoff = (size_t)b * (C1 * HW) + n0;
    const int qrow = (wid << 4) + (lane >> 2);
    for (int cc = 0; cc < 4; cc++) {
        float Y[8][4] = {};
#pragma unroll
        for (int s = 0; s < 4; s++) {
#pragma unroll
            for (int ch = 0; ch < 4; ch++) {
                int r = (cc << 6) + (ch << 4) + brow;
                int g = (s << 1) + bgsel;
                uint32_t b0, b1, b2, b3;
                ldsm4(b0, b1, b2, b3, sWo_u + r * 128 + ((g ^ (r & 7)) << 4));
                mma16816(Y[2 * ch], Of[s], b0, b1);
                mma16816(Y[2 * ch + 1], Of[s], b2, b3);
            }
        }
        if (cc) __syncthreads();
#pragma unroll
        for (int nt = 0; nt < 8; nt++) {
            int c = (nt << 3) + ((lane & 3) << 1);
            sY[c * LDY + qrow] = Y[nt][0];
            sY[(c + 1) * LDY + qrow] = Y[nt][1];
            sY[c * LDY + qrow + 8] = Y[nt][2];
            sY[(c + 1) * LDY + qrow + 8] = Y[nt][3];
        }
        __syncthreads();
        for (int i2 = tid; i2 < 8192; i2 += 256) {
            int c = i2 >> 7, q = i2 & 127;
            size_t gaddr = xoff + (size_t)((cc << 6) + c) * HW + q;
            out[gaddr] = x1[gaddr] + sY[c * LDY + q] + bo[(cc << 6) + c];
        }
    }
}

extern "C" void kernel_launch(void* const* d_in, const int* in_sizes, int n_in,
                              void* d_out, int out_size) {
    const float* x1 = (const float*)d_in[0];
    const float* x2 = (const float*)d_in[1];
    const float* Wq = (const float*)d_in[2];
    const float* bq = (const float*)d_in[3];
    const float* Wk = (const float*)d_in[4];
    const float* bk = (const float*)d_in[5];
    const float* Wv = (const float*)d_in[6];
    const float* bv = (const float*)d_in[7];
    const float* Wo = (const float*)d_in[8];
    const float* bo = (const float*)d_in[9];
    float* out = (float*)d_out;
    (void)in_sizes; (void)n_in; (void)out_size;

    static const int smem_attn = 32768 + 64 * LDY * 4;
    cudaFuncSetAttribute(attn_kernel, cudaFuncAttributeMaxDynamicSharedMemorySize,
                         smem_attn);

    pool_kernel<<<(NB * C2 * M) / 256, 256>>>(x2);
    kv_kernel<<<dim3(M / 64, NB), 256>>>(Wk, bk, Wv, bv);
    q_kernel<<<dim3(HW / 64, NB), 256>>>(x1, Wq, bq);
    attn_kernel<<<dim3(HW / 128, NB), 256, smem_attn>>>(x1, Wo, bo, out);
}

// round 3
// speedup vs baseline: 4.3853x; 1.3988x over previous
#include <cuda_runtime.h>
#include <cuda_bf16.h>
#include <cstdint>

#define NB 8
#define C1 256
#define C2 512
#define HW 4096
#define D  64
#define M  1024
#define LDY 132

// Scratch (device globals: allocation-free rule). All transposed: [b][d][*]
__device__ __nv_bfloat16 g_Qth[NB * D * HW];   // [b][d][n]  4 MB
__device__ __nv_bfloat16 g_Kth[NB * D * M];    // [b][d][m]  1 MB
__device__ __nv_bfloat16 g_Vth[NB * D * M];    // [b][d][m]  1 MB

__device__ __forceinline__ uint32_t pack_bf16(float a, float b) {
    __nv_bfloat162 h = __floats2bfloat162_rn(a, b);
    return *reinterpret_cast<uint32_t*>(&h);
}

__device__ __forceinline__ void ldsm4(uint32_t& r0, uint32_t& r1, uint32_t& r2,
                                      uint32_t& r3, uint32_t addr) {
    asm volatile("ldmatrix.sync.aligned.m8n8.x4.shared.b16 {%0,%1,%2,%3}, [%4];\n"
                 : "=r"(r0), "=r"(r1), "=r"(r2), "=r"(r3) : "r"(addr));
}
__device__ __forceinline__ void ldsm4t(uint32_t& r0, uint32_t& r1, uint32_t& r2,
                                       uint32_t& r3, uint32_t addr) {
    asm volatile("ldmatrix.sync.aligned.m8n8.x4.trans.shared.b16 {%0,%1,%2,%3}, [%4];\n"
                 : "=r"(r0), "=r"(r1), "=r"(r2), "=r"(r3) : "r"(addr));
}

__device__ __forceinline__ void mma16816(float c[4], const uint32_t a[4],
                                         uint32_t b0, uint32_t b1) {
    asm volatile("mma.sync.aligned.m16n8k16.row.col.f32.bf16.bf16.f32 "
                 "{%0,%1,%2,%3}, {%4,%5,%6,%7}, {%8,%9}, {%0,%1,%2,%3};\n"
                 : "+f"(c[0]), "+f"(c[1]), "+f"(c[2]), "+f"(c[3])
                 : "r"(a[0]), "r"(a[1]), "r"(a[2]), "r"(a[3]), "r"(b0), "r"(b1));
}

// ---------------- kernel 1: fused pool + K/V projection (tensor core) ----------------
// Kt[d][m] = sum_c Wk[d][c] * pool(x2)[c][m] + bk[d]; Vt likewise.
// CTA: (b, m-tile of 64). c-loop in chunks of 64.
__global__ __launch_bounds__(256) void kvproj_kernel(
        const float* __restrict__ x2,
        const float* __restrict__ Wk, const float* __restrict__ bk,
        const float* __restrict__ Wv, const float* __restrict__ bv) {
    __shared__ __align__(16) char sXb[64 * 128];   // bf16 [c][m], 128B rows, swizzled
    __shared__ __align__(16) char sWkb[64 * 128];  // bf16 [d][c]
    __shared__ __align__(16) char sWvb[64 * 128];
    const uint32_t sX_u = (uint32_t)__cvta_generic_to_shared(sXb);
    const uint32_t sWk_u = (uint32_t)__cvta_generic_to_shared(sWkb);
    const uint32_t sWv_u = (uint32_t)__cvta_generic_to_shared(sWvb);

    const int b = blockIdx.y, m0 = blockIdx.x << 6;
    const int tid = threadIdx.x, wid = tid >> 5, lane = tid & 31;
    const int dw = wid & 3, mw = wid >> 2;
    const int h2_0 = m0 >> 5;              // first pooled row of this m-tile

    float CK[4][4] = {}, CV[4][4] = {};

    for (int c0 = 0; c0 < C2; c0 += 64) {
        __syncthreads();
        // pooled x2 -> sX bf16 [c][m] (on-the-fly 2x2 mean)
        for (int i = tid; i < 2048; i += 256) {
            int c = i >> 5, t = i & 31;
            int h2l = t >> 4, j = t & 15;          // j: w2-pair -> m pair
            const float* s = x2 + ((size_t)(b * C2 + c0 + c) << 12)
                           + (((h2_0 + h2l) << 1) << 6) + (j << 2);
            float4 f0 = *(const float4*)s;
            float4 f1 = *(const float4*)(s + 64);
            float o0 = 0.25f * (f0.x + f0.y + f1.x + f1.y);
            float o1 = 0.25f * (f0.z + f0.w + f1.z + f1.w);
            int ml = (h2l << 5) + (j << 1);
            uint32_t phys = c * 128 + (((ml >> 3) ^ (c & 7)) << 4) + ((ml & 7) << 1);
            *(uint32_t*)(sXb + phys) = pack_bf16(o0, o1);
        }
        // weights fp32 -> bf16 smem [d][c]
        for (int i = tid; i < 1024; i += 256) {
            int d = i >> 4, pos = i & 15;
            float4 wk = *(const float4*)(Wk + d * C2 + c0 + (pos << 2));
            float4 wv = *(const float4*)(Wv + d * C2 + c0 + (pos << 2));
            uint32_t phys = d * 128 + (((pos >> 1) ^ (d & 7)) << 4) + ((pos & 1) << 3);
            *(uint2*)(sWkb + phys) = make_uint2(pack_bf16(wk.x, wk.y), pack_bf16(wk.z, wk.w));
            *(uint2*)(sWvb + phys) = make_uint2(pack_bf16(wv.x, wv.y), pack_bf16(wv.z, wv.w));
        }
        __syncthreads();

#pragma unroll
        for (int ks = 0; ks < 4; ks++) {
            // A fragments (normal ldmatrix, row-major [d][c])
            int ar = (dw << 4) + (lane & 15);
            int ag = (ks << 1) + (lane >> 4);
            uint32_t aoff = ar * 128 + ((ag ^ (ar & 7)) << 4);
            uint32_t Ak[4], Av[4];
            ldsm4(Ak[0], Ak[1], Ak[2], Ak[3], sWk_u + aoff);
            ldsm4(Av[0], Av[1], Av[2], Av[3], sWv_u + aoff);
            // B fragments (trans ldmatrix from [c][m])
            int krow = (ks << 4) + (lane & 7) + (((lane >> 3) & 1) << 3);
#pragma unroll
            for (int nt = 0; nt < 2; nt++) {
                int ncol = (mw << 5) + (nt << 4) + ((lane >> 4) << 3);
                uint32_t b0, b1, b2, b3;
                ldsm4t(b0, b1, b2, b3,
                       sX_u + krow * 128 + (((ncol >> 3) ^ (krow & 7)) << 4));
                mma16816(CK[2 * nt], Ak, b0, b1);
                mma16816(CK[2 * nt + 1], Ak, b2, b3);
                mma16816(CV[2 * nt], Av, b0, b1);
                mma16816(CV[2 * nt + 1], Av, b2, b3);
            }
        }
    }
    // epilogue: bias + pack + store Kt/Vt [b][d][1024]
    int row0 = (dw << 4) + (lane >> 2);
    float bk0 = bk[row0], bk1 = bk[row0 + 8];
    float bv0 = bv[row0], bv1 = bv[row0 + 8];
    __nv_bfloat16* Kp = g_Kth + ((size_t)b * 64 + row0) * M + m0;
    __nv_bfloat16* Vp = g_Vth + ((size_t)b * 64 + row0) * M + m0;
#pragma unroll
    for (int nt = 0; nt < 2; nt++)
#pragma unroll
        for (int h = 0; h < 2; h++) {
            int ci = 2 * nt + h;
            int ncol = (mw << 5) + (nt << 4) + (h << 3) + ((lane & 3) << 1);
            *(uint32_t*)(Kp + ncol) = pack_bf16(CK[ci][0] + bk0, CK[ci][1] + bk0);
            *(uint32_t*)(Kp + (size_t)8 * M + ncol) = pack_bf16(CK[ci][2] + bk1, CK[ci][3] + bk1);
            *(uint32_t*)(Vp + ncol) = pack_bf16(CV[ci][0] + bv0, CV[ci][1] + bv0);
            *(uint32_t*)(Vp + (size_t)8 * M + ncol) = pack_bf16(CV[ci][2] + bv1, CV[ci][3] + bv1);
        }
}

// ---------------- kernel 2: Q projection (tensor core) ----------------
// Qt[d][n] = sum_c Wq[d][c] * x1[c][n] + bq[d].  CTA: (b, n-tile of 128).
__global__ __launch_bounds__(256) void qproj_kernel(
        const float* __restrict__ x1, const float* __restrict__ Wq,
        const float* __restrict__ bq) {
    __shared__ __align__(16) char sXb[64 * 256];   // bf16 [c][n], 256B rows
    __shared__ __align__(16) char sWb[64 * 128];   // bf16 [d][c]
    const uint32_t sX_u = (uint32_t)__cvta_generic_to_shared(sXb);
    const uint32_t sW_u = (uint32_t)__cvta_generic_to_shared(sWb);

    const int b = blockIdx.y, n0 = blockIdx.x << 7;
    const int tid = threadIdx.x, wid = tid >> 5, lane = tid & 31;
    const int dw = wid & 3, nw = wid >> 2;

    float C[8][4] = {};

    for (int c0 = 0; c0 < C1; c0 += 64) {
        __syncthreads();
        for (int i = tid; i < 2048; i += 256) {
            int c = i >> 5, pos = i & 31;          // pos: 8-byte (4-elem) granule
            float4 f = *(const float4*)(x1 + ((size_t)(b * C1 + c0 + c) << 12) + n0 + (pos << 2));
            uint32_t phys = c * 256 + (((pos >> 1) ^ (c & 7)) << 4) + ((pos & 1) << 3);
            *(uint2*)(sXb + phys) = make_uint2(pack_bf16(f.x, f.y), pack_bf16(f.z, f.w));
        }
        for (int i = tid; i < 1024; i += 256) {
            int d = i >> 4, pos = i & 15;
            float4 w = *(const float4*)(Wq + d * C1 + c0 + (pos << 2));
            uint32_t phys = d * 128 + (((pos >> 1) ^ (d & 7)) << 4) + ((pos & 1) << 3);
            *(uint2*)(sWb + phys) = make_uint2(pack_bf16(w.x, w.y), pack_bf16(w.z, w.w));
        }
        __syncthreads();

#pragma unroll
        for (int ks = 0; ks < 4; ks++) {
            int ar = (dw << 4) + (lane & 15);
            int ag = (ks << 1) + (lane >> 4);
            uint32_t A[4];
            ldsm4(A[0], A[1], A[2], A[3], sW_u + ar * 128 + ((ag ^ (ar & 7)) << 4));
            int krow = (ks << 4) + (lane & 7) + (((lane >> 3) & 1) << 3);
#pragma unroll
            for (int nt = 0; nt < 4; nt++) {
                int ncol = (nw << 6) + (nt << 4) + ((lane >> 4) << 3);
                uint32_t b0, b1, b2, b3;
                ldsm4t(b0, b1, b2, b3,
                       sX_u + krow * 256 + (((ncol >> 3) ^ (krow & 7)) << 4));
                mma16816(C[2 * nt], A, b0, b1);
                mma16816(C[2 * nt + 1], A, b2, b3);
            }
        }
    }
    int row0 = (dw << 4) + (lane >> 2);
    float b0v = bq[row0], b1v = bq[row0 + 8];
    __nv_bfloat16* Qp = g_Qth + ((size_t)b * 64 + row0) * HW + n0;
#pragma unroll
    for (int nt = 0; nt < 4; nt++)
#pragma unroll
        for (int h = 0; h < 2; h++) {
            int ci = 2 * nt + h;
            int ncol = (nw << 6) + (nt << 4) + (h << 3) + ((lane & 3) << 1);
            *(uint32_t*)(Qp + ncol) = pack_bf16(C[ci][0] + b0v, C[ci][1] + b0v);
            *(uint32_t*)(Qp + (size_t)8 * HW + ncol) = pack_bf16(C[ci][2] + b1v, C[ci][3] + b1v);
        }
}

// ---------------- kernel 3: tensor-core attention + out-proj + residual ----------------
// CTA: 128 queries, 8 warps. K/V tiles of 64 keys, double-buffered.
// Smem: buffers B0=[0,16384) B1=[16384,32768) (each: sK 8KB + sV 8KB);
//       Q staging uses [0,16384) before the loop; phase B: sWo [0,32768), sY after.
__global__ __launch_bounds__(256, 2) void attn_kernel(
        const float* __restrict__ x1, const float* __restrict__ Wo,
        const float* __restrict__ bo, float* __restrict__ out) {
    extern __shared__ char sm[];
    char* sWo = sm;
    float* sY = (float*)(sm + 32768);

    const int b = blockIdx.y, n0 = blockIdx.x << 7;
    const int tid = threadIdx.x, wid = tid >> 5, lane = tid & 31;
    const uint32_t sm_u = (uint32_t)__cvta_generic_to_shared(sm);
    const uint32_t sWo_u = sm_u;

    const __nv_bfloat16* Qg = g_Qth + (size_t)b * 64 * HW + n0;   // [d][n]
    const __nv_bfloat16* Kg0 = g_Kth + (size_t)b * 64 * M;        // [d][m]
    const __nv_bfloat16* Vg0 = g_Vth + (size_t)b * 64 * M;        // [d][m]

    // ---- stage Qt tile [64 d][128 q] into sm[0,16384), K/V tile 0 into B1 ----
    for (int i = tid; i < 1024; i += 256) {
        int r = i >> 4, pos = i & 15;
        uint4 v = *(const uint4*)(Qg + (size_t)r * HW + (pos << 3));
        *(uint4*)(sm + r * 256 + ((pos ^ (r & 7)) << 4)) = v;
    }
    for (int i = tid; i < 512; i += 256) {
        int r = i >> 3, pos = i & 7;
        uint4 v = *(const uint4*)(Kg0 + (size_t)r * M + (pos << 3));
        *(uint4*)(sm + 16384 + r * 128 + ((pos ^ (r & 7)) << 4)) = v;
        uint4 w = *(const uint4*)(Vg0 + (size_t)r * M + (pos << 3));
        *(uint4*)(sm + 24576 + r * 128 + ((pos ^ (r & 7)) << 4)) = w;
    }
    __syncthreads();

    // ---- Q fragments via trans-ldmatrix (A-operand layout) ----
    uint32_t Qf[4][4];
    {
        int mcol = (wid << 4) + (((lane >> 3) & 1) << 3);
#pragma unroll
        for (int s = 0; s < 4; s++) {
            int krow = (s << 4) + (lane & 7) + ((lane >> 4) << 3);
            ldsm4t(Qf[s][0], Qf[s][1], Qf[s][2], Qf[s][3],
                   sm_u + krow * 256 + (((mcol >> 3) ^ (krow & 7)) << 4));
        }
    }
    __syncthreads();   // sm[0,16384) now reusable as buffer B0

    float O[8][4] = {};
    float l0 = 0.f, l1 = 0.f;

    const int brow = (lane & 7) + ((lane >> 4) << 3);   // V (normal ldsm) row piece
    const int bgsel = (lane >> 3) & 1;
    const int tkrow = (lane & 7) + (((lane >> 3) & 1) << 3);  // K (trans ldsm) row piece
    const int tnsel = (lane >> 4) << 3;

    for (int kt = 0; kt < 16; kt++) {
        uint32_t cbase = sm_u + (((kt & 1) ^ 1) << 14);   // tile kt buffer
        // prefetch tile kt+1 into the other buffer
        if (kt < 15) {
            char* pb = sm + ((kt & 1) << 14);
            const __nv_bfloat16* Kg = Kg0 + (kt + 1) * 64;
            const __nv_bfloat16* Vg = Vg0 + (kt + 1) * 64;
            for (int i = tid; i < 512; i += 256) {
                int r = i >> 3, pos = i & 7;
                uint4 v = *(const uint4*)(Kg + (size_t)r * M + (pos << 3));
                *(uint4*)(pb + r * 128 + ((pos ^ (r & 7)) << 4)) = v;
                uint4 w = *(const uint4*)(Vg + (size_t)r * M + (pos << 3));
                *(uint4*)(pb + 8192 + r * 128 + ((pos ^ (r & 7)) << 4)) = w;
            }
        }
        // ---- S = Q K^T  (K via trans-ldmatrix from [d][key]) ----
        float S[8][4] = {};
#pragma unroll
        for (int s = 0; s < 4; s++) {
            int krow = (s << 4) + tkrow;
            uint32_t rb = cbase + krow * 128;
            int r7x = (krow & 7);
#pragma unroll
            for (int nh = 0; nh < 4; nh++) {
                int ncol = (nh << 4) + tnsel;
                uint32_t b0, b1, b2, b3;
                ldsm4t(b0, b1, b2, b3, rb + (((ncol >> 3) ^ r7x) << 4));
                mma16816(S[2 * nh], Qf[s], b0, b1);
                mma16816(S[2 * nh + 1], Qf[s], b2, b3);
            }
        }
        // ---- softmax numerator ----
        uint32_t Pf[4][4];
#pragma unroll
        for (int nt = 0; nt < 8; nt++) {
#pragma unroll
            for (int j = 0; j < 4; j++) S[nt][j] = __expf(S[nt][j]);
            l0 += S[nt][0] + S[nt][1];
            l1 += S[nt][2] + S[nt][3];
        }
#pragma unroll
        for (int kk = 0; kk < 4; kk++) {
            Pf[kk][0] = pack_bf16(S[2 * kk][0], S[2 * kk][1]);
            Pf[kk][1] = pack_bf16(S[2 * kk][2], S[2 * kk][3]);
            Pf[kk][2] = pack_bf16(S[2 * kk + 1][0], S[2 * kk + 1][1]);
            Pf[kk][3] = pack_bf16(S[2 * kk + 1][2], S[2 * kk + 1][3]);
        }
        // ---- O += P V  (V normal ldsm from [d][key]) ----
        uint32_t vbase = cbase + 8192;
#pragma unroll
        for (int kk = 0; kk < 4; kk++) {
#pragma unroll
            for (int dh = 0; dh < 4; dh++) {
                int r = (dh << 4) + brow;
                int g = (kk << 1) + bgsel;
                uint32_t b0, b1, b2, b3;
                ldsm4(b0, b1, b2, b3, vbase + r * 128 + ((g ^ (r & 7)) << 4));
                mma16816(O[2 * dh], Pf[kk], b0, b1);
                mma16816(O[2 * dh + 1], Pf[kk], b2, b3);
            }
        }
        __syncthreads();
    }

    // ---- normalize, build O fragments ----
    l0 += __shfl_xor_sync(0xffffffffu, l0, 1);
    l0 += __shfl_xor_sync(0xffffffffu, l0, 2);
    l1 += __shfl_xor_sync(0xffffffffu, l1, 1);
    l1 += __shfl_xor_sync(0xffffffffu, l1, 2);
    float inv0 = 1.0f / l0, inv1 = 1.0f / l1;
    uint32_t Of[4][4];
#pragma unroll
    for (int s = 0; s < 4; s++) {
        Of[s][0] = pack_bf16(O[2 * s][0] * inv0, O[2 * s][1] * inv0);
        Of[s][1] = pack_bf16(O[2 * s][2] * inv1, O[2 * s][3] * inv1);
        Of[s][2] = pack_bf16(O[2 * s + 1][0] * inv0, O[2 * s + 1][1] * inv0);
        Of[s][3] = pack_bf16(O[2 * s + 1][2] * inv1, O[2 * s + 1][3] * inv1);
    }

    // ---- phase B: Wo (fp32 -> bf16, swizzled) ----
    for (int i = tid; i < 2048; i += 256) {
        int c = i >> 3, g = i & 7;
        const float4* wp = (const float4*)(Wo + c * 64 + g * 8);
        float4 w0 = wp[0], w1 = wp[1];
        uint4 v;
        v.x = pack_bf16(w0.x, w0.y);
        v.y = pack_bf16(w0.z, w0.w);
        v.z = pack_bf16(w1.x, w1.y);
        v.w = pack_bf16(w1.z, w1.w);
        *(uint4*)(sWo + c * 128 + ((g ^ (c & 7)) << 4)) = v;
    }
    __syncthreads();

    const size_t xoff = (size_t)b * (C1 * HW) + n0;
    const int qrow = (wid << 4) + (lane >> 2);
    for (int cc = 0; cc < 4; cc++) {
        float Y[8][4] = {};
#pragma unroll
        for (int s = 0; s < 4; s++) {
#pragma unroll
            for (int ch = 0; ch < 4; ch++) {
                int r = (cc << 6) + (ch << 4) + brow;
                int g = (s << 1) + bgsel;
                uint32_t b0, b1, b2, b3;
                ldsm4(b0, b1, b2, b3, sWo_u + r * 128 + ((g ^ (r & 7)) << 4));
                mma16816(Y[2 * ch], Of[s], b0, b1);
                mma16816(Y[2 * ch + 1], Of[s], b2, b3);
            }
        }
        if (cc) __syncthreads();
#pragma unroll
        for (int nt = 0; nt < 8; nt++) {
            int c = (nt << 3) + ((lane & 3) << 1);
            sY[c * LDY + qrow] = Y[nt][0];
            sY[(c + 1) * LDY + qrow] = Y[nt][1];
            sY[c * LDY + qrow + 8] = Y[nt][2];
            sY[(c + 1) * LDY + qrow + 8] = Y[nt][3];
        }
        __syncthreads();
        for (int i2 = tid; i2 < 8192; i2 += 256) {
            int c = i2 >> 7, q = i2 & 127;
            size_t gaddr = xoff + (size_t)((cc << 6) + c) * HW + q;
            out[gaddr] = x1[gaddr] + sY[c * LDY + q] + bo[(cc << 6) + c];
        }
    }
}

extern "C" void kernel_launch(void* const* d_in, const int* in_sizes, int n_in,
                              void* d_out, int out_size) {
    const float* x1 = (const float*)d_in[0];
    const float* x2 = (const float*)d_in[1];
    const float* Wq = (const float*)d_in[2];
    const float* bq = (const float*)d_in[3];
    const float* Wk = (const float*)d_in[4];
    const float* bk = (const float*)d_in[5];
    const float* Wv = (const float*)d_in[6];
    const float* bv = (const float*)d_in[7];
    const float* Wo = (const float*)d_in[8];
    const float* bo = (const float*)d_in[9];
    float* out = (float*)d_out;
    (void)in_sizes; (void)n_in; (void)out_size;

    static const int smem_attn = 32768 + 64 * LDY * 4;
    cudaFuncSetAttribute(attn_kernel, cudaFuncAttributeMaxDynamicSharedMemorySize,
                         smem_attn);

    kvproj_kernel<<<dim3(M / 64, NB), 256>>>(x2, Wk, bk, Wv, bv);
    qproj_kernel<<<dim3(HW / 128, NB), 256>>>(x1, Wq, bq);
    attn_kernel<<<dim3(HW / 128, NB), 256, smem_attn>>>(x1, Wo, bo, out);
}

// round 4
// speedup vs baseline: 5.7458x; 1.3102x over previous
#include <cuda_runtime.h>
#include <cuda_bf16.h>
#include <cstdint>

#define NB 8
#define C1 256
#define C2 512
#define HW 4096
#define D  64
#define M  1024
#define LDY 132

// Scratch (device globals: allocation-free rule)
__device__ __align__(16) __nv_bfloat16 g_x2ph[NB * C2 * M];  // pooled x2, bf16, 8 MB
__device__ __align__(16) __nv_bfloat16 g_Qth[NB * D * HW];   // [b][d][n]
__device__ __align__(16) __nv_bfloat16 g_Kth[NB * D * M];    // [b][d][m]
__device__ __align__(16) __nv_bfloat16 g_Vth[NB * D * M];    // [b][d][m]
__device__ __align__(16) __nv_bfloat16 g_Wkh[D * C2];
__device__ __align__(16) __nv_bfloat16 g_Wvh[D * C2];
__device__ __align__(16) __nv_bfloat16 g_Wqh[D * C1];
__device__ __align__(16) __nv_bfloat16 g_Woh[C1 * D];

__device__ __forceinline__ uint32_t pack_bf16(float a, float b) {
    __nv_bfloat162 h = __floats2bfloat162_rn(a, b);
    return *reinterpret_cast<uint32_t*>(&h);
}

__device__ __forceinline__ void ldsm4(uint32_t& r0, uint32_t& r1, uint32_t& r2,
                                      uint32_t& r3, uint32_t addr) {
    asm volatile("ldmatrix.sync.aligned.m8n8.x4.shared.b16 {%0,%1,%2,%3}, [%4];\n"
                 : "=r"(r0), "=r"(r1), "=r"(r2), "=r"(r3) : "r"(addr));
}
__device__ __forceinline__ void ldsm4t(uint32_t& r0, uint32_t& r1, uint32_t& r2,
                                       uint32_t& r3, uint32_t addr) {
    asm volatile("ldmatrix.sync.aligned.m8n8.x4.trans.shared.b16 {%0,%1,%2,%3}, [%4];\n"
                 : "=r"(r0), "=r"(r1), "=r"(r2), "=r"(r3) : "r"(addr));
}
__device__ __forceinline__ void mma16816(float c[4], const uint32_t a[4],
                                         uint32_t b0, uint32_t b1) {
    asm volatile("mma.sync.aligned.m16n8k16.row.col.f32.bf16.bf16.f32 "
                 "{%0,%1,%2,%3}, {%4,%5,%6,%7}, {%8,%9}, {%0,%1,%2,%3};\n"
                 : "+f"(c[0]), "+f"(c[1]), "+f"(c[2]), "+f"(c[3])
                 : "r"(a[0]), "r"(a[1]), "r"(a[2]), "r"(a[3]), "r"(b0), "r"(b1));
}
__device__ __forceinline__ void cp16(uint32_t saddr, const void* g) {
    asm volatile("cp.async.cg.shared.global [%0], [%1], 16;\n" :: "r"(saddr), "l"(g));
}
__device__ __forceinline__ void cp_commit() { asm volatile("cp.async.commit_group;\n"); }
__device__ __forceinline__ void cp_wait0() { asm volatile("cp.async.wait_group 0;\n"); }

// ---------------- kernel A: weights fp32 -> bf16 ----------------
__global__ void wprep_kernel(const float* __restrict__ Wk, const float* __restrict__ Wv,
                             const float* __restrict__ Wq, const float* __restrict__ Wo) {
    int i = blockIdx.x * 256 + threadIdx.x;   // 98304 total
    if (i < 32768)      g_Wkh[i] = __float2bfloat16(Wk[i]);
    else if (i < 65536) g_Wvh[i - 32768] = __float2bfloat16(Wv[i - 32768]);
    else if (i < 81920) g_Wqh[i - 65536] = __float2bfloat16(Wq[i - 65536]);
    else                g_Woh[i - 81920] = __float2bfloat16(Wo[i - 81920]);
}

// ---------------- kernel B: streaming 2x2 pool, fp32 -> bf16 ----------------
__global__ void pool_kernel(const float* __restrict__ x2) {
    int i = blockIdx.x * 256 + threadIdx.x;   // 2,097,152 threads, 2 outputs each
    int j = i & 15, h2 = (i >> 4) & 31, bc = i >> 9;
    const float* s = x2 + ((size_t)bc << 12) + (h2 << 7) + (j << 2);
    float4 f0 = *(const float4*)s;
    float4 f1 = *(const float4*)(s + 64);
    uint32_t p = pack_bf16(0.25f * (f0.x + f0.y + f1.x + f1.y),
                           0.25f * (f0.z + f0.w + f1.z + f1.w));
    *(uint32_t*)(g_x2ph + ((size_t)bc << 10) + (h2 << 5) + (j << 1)) = p;
}

// ---------------- kernel C: K/V projection (all-bf16 staging) ----------------
__global__ __launch_bounds__(256) void kvproj_kernel(
        const float* __restrict__ bk, const float* __restrict__ bv) {
    __shared__ __align__(16) char sXb[64 * 128];
    __shared__ __align__(16) char sWkb[64 * 128];
    __shared__ __align__(16) char sWvb[64 * 128];
    const uint32_t sX_u = (uint32_t)__cvta_generic_to_shared(sXb);
    const uint32_t sWk_u = (uint32_t)__cvta_generic_to_shared(sWkb);
    const uint32_t sWv_u = (uint32_t)__cvta_generic_to_shared(sWvb);

    const int b = blockIdx.y, m0 = blockIdx.x << 6;
    const int tid = threadIdx.x, wid = tid >> 5, lane = tid & 31;
    const int dw = wid & 3, mw = wid >> 2;

    float CK[4][4] = {}, CV[4][4] = {};

    for (int c0 = 0; c0 < C2; c0 += 64) {
        __syncthreads();
        for (int i = tid; i < 512; i += 256) {
            int r = i >> 3, pos = i & 7;
            uint32_t sw = ((pos ^ (r & 7)) << 4);
            cp16(sX_u + r * 128 + sw,
                 g_x2ph + ((size_t)(b * C2 + c0 + r) << 10) + m0 + (pos << 3));
            cp16(sWk_u + r * 128 + sw, g_Wkh + r * C2 + c0 + (pos << 3));
            cp16(sWv_u + r * 128 + sw, g_Wvh + r * C2 + c0 + (pos << 3));
        }
        cp_commit(); cp_wait0();
        __syncthreads();

#pragma unroll
        for (int ks = 0; ks < 4; ks++) {
            int ar = (dw << 4) + (lane & 15);
            int ag = (ks << 1) + (lane >> 4);
            uint32_t aoff = ar * 128 + ((ag ^ (ar & 7)) << 4);
            uint32_t Ak[4], Av[4];
            ldsm4(Ak[0], Ak[1], Ak[2], Ak[3], sWk_u + aoff);
            ldsm4(Av[0], Av[1], Av[2], Av[3], sWv_u + aoff);
            int krow = (ks << 4) + (lane & 7) + (((lane >> 3) & 1) << 3);
#pragma unroll
            for (int nt = 0; nt < 2; nt++) {
                int ncol = (mw << 5) + (nt << 4) + ((lane >> 4) << 3);
                uint32_t b0, b1, b2, b3;
                ldsm4t(b0, b1, b2, b3,
                       sX_u + krow * 128 + (((ncol >> 3) ^ (krow & 7)) << 4));
                mma16816(CK[2 * nt], Ak, b0, b1);
                mma16816(CK[2 * nt + 1], Ak, b2, b3);
                mma16816(CV[2 * nt], Av, b0, b1);
                mma16816(CV[2 * nt + 1], Av, b2, b3);
            }
        }
    }
    int row0 = (dw << 4) + (lane >> 2);
    float bk0 = bk[row0], bk1 = bk[row0 + 8];
    float bv0 = bv[row0], bv1 = bv[row0 + 8];
    __nv_bfloat16* Kp = g_Kth + ((size_t)b * 64 + row0) * M + m0;
    __nv_bfloat16* Vp = g_Vth + ((size_t)b * 64 + row0) * M + m0;
#pragma unroll
    for (int nt = 0; nt < 2; nt++)
#pragma unroll
        for (int h = 0; h < 2; h++) {
            int ci = 2 * nt + h;
            int ncol = (mw << 5) + (nt << 4) + (h << 3) + ((lane & 3) << 1);
            *(uint32_t*)(Kp + ncol) = pack_bf16(CK[ci][0] + bk0, CK[ci][1] + bk0);
            *(uint32_t*)(Kp + (size_t)8 * M + ncol) = pack_bf16(CK[ci][2] + bk1, CK[ci][3] + bk1);
            *(uint32_t*)(Vp + ncol) = pack_bf16(CV[ci][0] + bv0, CV[ci][1] + bv0);
            *(uint32_t*)(Vp + (size_t)8 * M + ncol) = pack_bf16(CV[ci][2] + bv1, CV[ci][3] + bv1);
        }
}

// ---------------- kernel D: Q projection (n-tile 64, grid 512) ----------------
__global__ __launch_bounds__(256) void qproj_kernel(
        const float* __restrict__ x1, const float* __restrict__ bq) {
    __shared__ __align__(16) char sXb[64 * 128];   // bf16 [c][n64]
    __shared__ __align__(16) char sWb[64 * 128];   // bf16 [d][c64]
    const uint32_t sX_u = (uint32_t)__cvta_generic_to_shared(sXb);
    const uint32_t sW_u = (uint32_t)__cvta_generic_to_shared(sWb);

    const int b = blockIdx.y, n0 = blockIdx.x << 6;
    const int tid = threadIdx.x, wid = tid >> 5, lane = tid & 31;
    const int dw = wid & 3, mw = wid >> 2;

    float C[4][4] = {};

    for (int c0 = 0; c0 < C1; c0 += 64) {
        __syncthreads();
        // x1 fp32 -> bf16 (convert in regs; 4 iters/thread, MLP ok)
        for (int i = tid; i < 1024; i += 256) {
            int r = i >> 4, p4 = i & 15;
            float4 f = *(const float4*)(x1 + ((size_t)(b * C1 + c0 + r) << 12) + n0 + (p4 << 2));
            uint32_t phys = r * 128 + (((p4 >> 1) ^ (r & 7)) << 4) + ((p4 & 1) << 3);
            *(uint2*)(sXb + phys) = make_uint2(pack_bf16(f.x, f.y), pack_bf16(f.z, f.w));
        }
        for (int i = tid; i < 512; i += 256) {
            int r = i >> 3, pos = i & 7;
            cp16(sW_u + r * 128 + ((pos ^ (r & 7)) << 4), g_Wqh + r * C1 + c0 + (pos << 3));
        }
        cp_commit(); cp_wait0();
        __syncthreads();

#pragma unroll
        for (int ks = 0; ks < 4; ks++) {
            int ar = (dw << 4) + (lane & 15);
            int ag = (ks << 1) + (lane >> 4);
            uint32_t A[4];
            ldsm4(A[0], A[1], A[2], A[3], sW_u + ar * 128 + ((ag ^ (ar & 7)) << 4));
            int krow = (ks << 4) + (lane & 7) + (((lane >> 3) & 1) << 3);
#pragma unroll
            for (int nt = 0; nt < 2; nt++) {
                int ncol = (mw << 5) + (nt << 4) + ((lane >> 4) << 3);
                uint32_t b0, b1, b2, b3;
                ldsm4t(b0, b1, b2, b3,
                       sX_u + krow * 128 + (((ncol >> 3) ^ (krow & 7)) << 4));
                mma16816(C[2 * nt], A, b0, b1);
                mma16816(C[2 * nt + 1], A, b2, b3);
            }
        }
    }
    int row0 = (dw << 4) + (lane >> 2);
    float b0v = bq[row0], b1v = bq[row0 + 8];
    __nv_bfloat16* Qp = g_Qth + ((size_t)b * 64 + row0) * HW + n0;
#pragma unroll
    for (int nt = 0; nt < 2; nt++)
#pragma unroll
        for (int h = 0; h < 2; h++) {
            int ci = 2 * nt + h;
            int ncol = (mw << 5) + (nt << 4) + (h << 3) + ((lane & 3) << 1);
            *(uint32_t*)(Qp + ncol) = pack_bf16(C[ci][0] + b0v, C[ci][1] + b0v);
            *(uint32_t*)(Qp + (size_t)8 * HW + ncol) = pack_bf16(C[ci][2] + b1v, C[ci][3] + b1v);
        }
}

// ---------------- kernel E: attention + out-proj + residual ----------------
__global__ __launch_bounds__(256, 2) void attn_kernel(
        const float* __restrict__ x1, const float* __restrict__ bo,
        float* __restrict__ out) {
    extern __shared__ char sm[];
    float* sY = (float*)(sm + 32768);

    const int b = blockIdx.y, n0 = blockIdx.x << 7;
    const int tid = threadIdx.x, wid = tid >> 5, lane = tid & 31;
    const uint32_t sm_u = (uint32_t)__cvta_generic_to_shared(sm);

    const __nv_bfloat16* Qg = g_Qth + (size_t)b * 64 * HW + n0;
    const __nv_bfloat16* Kg0 = g_Kth + (size_t)b * 64 * M;
    const __nv_bfloat16* Vg0 = g_Vth + (size_t)b * 64 * M;

    // stage Qt [64][128] into sm[0,16K) + K/V tile 0 into B1, via cp.async
    for (int i = tid; i < 1024; i += 256) {
        int r = i >> 4, pos = i & 15;
        cp16(sm_u + r * 256 + ((pos ^ (r & 7)) << 4), Qg + (size_t)r * HW + (pos << 3));
    }
    for (int i = tid; i < 512; i += 256) {
        int r = i >> 3, pos = i & 7;
        uint32_t sw = ((pos ^ (r & 7)) << 4);
        cp16(sm_u + 16384 + r * 128 + sw, Kg0 + (size_t)r * M + (pos << 3));
        cp16(sm_u + 24576 + r * 128 + sw, Vg0 + (size_t)r * M + (pos << 3));
    }
    cp_commit(); cp_wait0();
    __syncthreads();

    // Q fragments via trans-ldmatrix
    uint32_t Qf[4][4];
    {
        int mcol = (wid << 4) + (((lane >> 3) & 1) << 3);
#pragma unroll
        for (int s = 0; s < 4; s++) {
            int krow = (s << 4) + (lane & 7) + ((lane >> 4) << 3);
            ldsm4t(Qf[s][0], Qf[s][1], Qf[s][2], Qf[s][3],
                   sm_u + krow * 256 + (((mcol >> 3) ^ (krow & 7)) << 4));
        }
    }
    __syncthreads();   // sm[0,16K) -> buffer B0

    float O[8][4] = {};
    float l0 = 0.f, l1 = 0.f;

    const int brow = (lane & 7) + ((lane >> 4) << 3);
    const int bgsel = (lane >> 3) & 1;
    const int tkrow = (lane & 7) + (((lane >> 3) & 1) << 3);
    const int tnsel = (lane >> 4) << 3;

    for (int kt = 0; kt < 16; kt++) {
        uint32_t cbase = sm_u + (((kt & 1) ^ 1) << 14);
        // prefetch next K/V tile (or Wo upper half on the last tile)
        if (kt < 15) {
            uint32_t pb = sm_u + ((kt & 1) << 14);
            const __nv_bfloat16* Kg = Kg0 + (kt + 1) * 64;
            const __nv_bfloat16* Vg = Vg0 + (kt + 1) * 64;
            for (int i = tid; i < 512; i += 256) {
                int r = i >> 3, pos = i & 7;
                uint32_t sw = ((pos ^ (r & 7)) << 4);
                cp16(pb + r * 128 + sw, Kg + (size_t)r * M + (pos << 3));
                cp16(pb + 8192 + r * 128 + sw, Vg + (size_t)r * M + (pos << 3));
            }
        } else {
            // kt==15 computes on B0; B1 free -> Wo rows 128..255
            for (int i = tid; i < 1024; i += 256) {
                int r = 128 + (i >> 3), pos = i & 7;
                cp16(sm_u + r * 128 + ((pos ^ (r & 7)) << 4), g_Woh + r * 64 + (pos << 3));
            }
        }
        cp_commit();

        // S = Q K^T
        float S[8][4] = {};
#pragma unroll
        for (int s = 0; s < 4; s++) {
            int krow = (s << 4) + tkrow;
            uint32_t rb = cbase + krow * 128;
            int r7x = (krow & 7);
#pragma unroll
            for (int nh = 0; nh < 4; nh++) {
                int ncol = (nh << 4) + tnsel;
                uint32_t b0, b1, b2, b3;
                ldsm4t(b0, b1, b2, b3, rb + (((ncol >> 3) ^ r7x) << 4));
                mma16816(S[2 * nh], Qf[s], b0, b1);
                mma16816(S[2 * nh + 1], Qf[s], b2, b3);
            }
        }
        // softmax numerator
        uint32_t Pf[4][4];
#pragma unroll
        for (int nt = 0; nt < 8; nt++) {
#pragma unroll
            for (int j = 0; j < 4; j++) S[nt][j] = __expf(S[nt][j]);
            l0 += S[nt][0] + S[nt][1];
            l1 += S[nt][2] + S[nt][3];
        }
#pragma unroll
        for (int kk = 0; kk < 4; kk++) {
            Pf[kk][0] = pack_bf16(S[2 * kk][0], S[2 * kk][1]);
            Pf[kk][1] = pack_bf16(S[2 * kk][2], S[2 * kk][3]);
            Pf[kk][2] = pack_bf16(S[2 * kk + 1][0], S[2 * kk + 1][1]);
            Pf[kk][3] = pack_bf16(S[2 * kk + 1][2], S[2 * kk + 1][3]);
        }
        // O += P V
        uint32_t vbase = cbase + 8192;
#pragma unroll
        for (int kk = 0; kk < 4; kk++) {
#pragma unroll
            for (int dh = 0; dh < 4; dh++) {
                int r = (dh << 4) + brow;
                int g = (kk << 1) + bgsel;
                uint32_t b0, b1, b2, b3;
                ldsm4(b0, b1, b2, b3, vbase + r * 128 + ((g ^ (r & 7)) << 4));
                mma16816(O[2 * dh], Pf[kk], b0, b1);
                mma16816(O[2 * dh + 1], Pf[kk], b2, b3);
            }
        }
        cp_wait0();
        __syncthreads();
    }

    // normalize, build O fragments
    l0 += __shfl_xor_sync(0xffffffffu, l0, 1);
    l0 += __shfl_xor_sync(0xffffffffu, l0, 2);
    l1 += __shfl_xor_sync(0xffffffffu, l1, 1);
    l1 += __shfl_xor_sync(0xffffffffu, l1, 2);
    float inv0 = 1.0f / l0, inv1 = 1.0f / l1;
    uint32_t Of[4][4];
#pragma unroll
    for (int s = 0; s < 4; s++) {
        Of[s][0] = pack_bf16(O[2 * s][0] * inv0, O[2 * s][1] * inv0);
        Of[s][1] = pack_bf16(O[2 * s][2] * inv1, O[2 * s][3] * inv1);
        Of[s][2] = pack_bf16(O[2 * s + 1][0] * inv0, O[2 * s + 1][1] * inv0);
        Of[s][3] = pack_bf16(O[2 * s + 1][2] * inv1, O[2 * s + 1][3] * inv1);
    }

    // stage Wo rows 0..127 into B0 (upper half already resident in B1)
    for (int i = tid; i < 1024; i += 256) {
        int r = i >> 3, pos = i & 7;
        cp16(sm_u + r * 128 + ((pos ^ (r & 7)) << 4), g_Woh + r * 64 + (pos << 3));
    }
    cp_commit(); cp_wait0();
    __syncthreads();

    const size_t xoff = (size_t)b * (C1 * HW) + n0;
    const int qrow = (wid << 4) + (lane >> 2);
    for (int cc = 0; cc < 4; cc++) {
        float Y[8][4] = {};
#pragma unroll
        for (int s = 0; s < 4; s++) {
#pragma unroll
            for (int ch = 0; ch < 4; ch++) {
                int r = (cc << 6) + (ch << 4) + brow;
                int g = (s << 1) + bgsel;
                uint32_t b0, b1, b2, b3;
                ldsm4(b0, b1, b2, b3, sm_u + r * 128 + ((g ^ (r & 7)) << 4));
                mma16816(Y[2 * ch], Of[s], b0, b1);
                mma16816(Y[2 * ch + 1], Of[s], b2, b3);
            }
        }
        if (cc) __syncthreads();
#pragma unroll
        for (int nt = 0; nt < 8; nt++) {
            int c = (nt << 3) + ((lane & 3) << 1);
            sY[c * LDY + qrow] = Y[nt][0];
            sY[(c + 1) * LDY + qrow] = Y[nt][1];
            sY[c * LDY + qrow + 8] = Y[nt][2];
            sY[(c + 1) * LDY + qrow + 8] = Y[nt][3];
        }
        __syncthreads();
        for (int i2 = tid; i2 < 8192; i2 += 256) {
            int c = i2 >> 7, q = i2 & 127;
            size_t gaddr = xoff + (size_t)((cc << 6) + c) * HW + q;
            out[gaddr] = x1[gaddr] + sY[c * LDY + q] + bo[(cc << 6) + c];
        }
    }
}

extern "C" void kernel_launch(void* const* d_in, const int* in_sizes, int n_in,
                              void* d_out, int out_size) {
    const float* x1 = (const float*)d_in[0];
    const float* x2 = (const float*)d_in[1];
    const float* Wq = (const float*)d_in[2];
    const float* bq = (const float*)d_in[3];
    const float* Wk = (const float*)d_in[4];
    const float* bk = (const float*)d_in[5];
    const float* Wv = (const float*)d_in[6];
    const float* bv = (const float*)d_in[7];
    const float* Wo = (const float*)d_in[8];
    const float* bo = (const float*)d_in[9];
    float* out = (float*)d_out;
    (void)in_sizes; (void)n_in; (void)out_size; (void)Wo;

    static const int smem_attn = 32768 + 64 * LDY * 4;
    cudaFuncSetAttribute(attn_kernel, cudaFuncAttributeMaxDynamicSharedMemorySize,
                         smem_attn);

    wprep_kernel<<<384, 256>>>(Wk, Wv, Wq, Wo);
    pool_kernel<<<8192, 256>>>(x2);
    kvproj_kernel<<<dim3(M / 64, NB), 256>>>(bk, bv);
    qproj_kernel<<<dim3(HW / 64, NB), 256>>>(x1, bq);
    attn_kernel<<<dim3(HW / 128, NB), 256, smem_attn>>>(x1, bo, out);
}

// round 6
// speedup vs baseline: 6.6702x; 1.1609x over previous
#include <cuda_runtime.h>
#include <cuda_bf16.h>
#include <cstdint>

#define NB 8
#define C1 256
#define C2 512
#define HW 4096
#define D  64
#define M  1024
#define LDY 132
#define LOG2E 1.4426950408889634f

// Scratch (device globals: allocation-free rule)
__device__ __align__(16) __nv_bfloat16 g_x2ph[NB * C2 * M];  // pooled x2, bf16
__device__ __align__(16) __nv_bfloat16 g_Qth[NB * D * HW];   // [b][d][n]
__device__ __align__(16) __nv_bfloat16 g_Kth[NB * D * M];    // [b][d][m], pre-scaled by log2e
__device__ __align__(16) __nv_bfloat16 g_Vth[NB * D * M];    // [b][d][m]
__device__ __align__(16) __nv_bfloat16 g_Wkh[D * C2];
__device__ __align__(16) __nv_bfloat16 g_Wvh[D * C2];
__device__ __align__(16) __nv_bfloat16 g_Wqh[D * C1];
__device__ __align__(16) __nv_bfloat16 g_Woh[C1 * D];

__device__ __forceinline__ uint32_t pack_bf16(float a, float b) {
    __nv_bfloat162 h = __floats2bfloat162_rn(a, b);
    return *reinterpret_cast<uint32_t*>(&h);
}
__device__ __forceinline__ float ex2f(float x) {
    float y;
    asm("ex2.approx.f32 %0, %1;" : "=f"(y) : "f"(x));
    return y;
}
__device__ __forceinline__ void ldsm4(uint32_t& r0, uint32_t& r1, uint32_t& r2,
                                      uint32_t& r3, uint32_t addr) {
    asm volatile("ldmatrix.sync.aligned.m8n8.x4.shared.b16 {%0,%1,%2,%3}, [%4];\n"
                 : "=r"(r0), "=r"(r1), "=r"(r2), "=r"(r3) : "r"(addr));
}
__device__ __forceinline__ void ldsm4t(uint32_t& r0, uint32_t& r1, uint32_t& r2,
                                       uint32_t& r3, uint32_t addr) {
    asm volatile("ldmatrix.sync.aligned.m8n8.x4.trans.shared.b16 {%0,%1,%2,%3}, [%4];\n"
                 : "=r"(r0), "=r"(r1), "=r"(r2), "=r"(r3) : "r"(addr));
}
__device__ __forceinline__ void mma16816(float c[4], const uint32_t a[4],
                                         uint32_t b0, uint32_t b1) {
    asm volatile("mma.sync.aligned.m16n8k16.row.col.f32.bf16.bf16.f32 "
                 "{%0,%1,%2,%3}, {%4,%5,%6,%7}, {%8,%9}, {%0,%1,%2,%3};\n"
                 : "+f"(c[0]), "+f"(c[1]), "+f"(c[2]), "+f"(c[3])
                 : "r"(a[0]), "r"(a[1]), "r"(a[2]), "r"(a[3]), "r"(b0), "r"(b1));
}
__device__ __forceinline__ void cp16(uint32_t saddr, const void* g) {
    asm volatile("cp.async.cg.shared.global [%0], [%1], 16;\n" :: "r"(saddr), "l"(g));
}
__device__ __forceinline__ void cp_commit() { asm volatile("cp.async.commit_group;\n"); }
__device__ __forceinline__ void cp_wait0() { asm volatile("cp.async.wait_group 0;\n"); }

// ---------------- kernel A: pool (blocks < 8192) + weight cvt (rest) ----------------
__global__ void prep_kernel(const float* __restrict__ x2,
                            const float* __restrict__ Wk, const float* __restrict__ Wv,
                            const float* __restrict__ Wq, const float* __restrict__ Wo) {
    if (blockIdx.x < 8192) {
        int i = blockIdx.x * 256 + threadIdx.x;
        int j = i & 15, h2 = (i >> 4) & 31, bc = i >> 9;
        const float* s = x2 + ((size_t)bc << 12) + (h2 << 7) + (j << 2);
        float4 f0 = *(const float4*)s;
        float4 f1 = *(const float4*)(s + 64);
        uint32_t p = pack_bf16(0.25f * (f0.x + f0.y + f1.x + f1.y),
                               0.25f * (f0.z + f0.w + f1.z + f1.w));
        *(uint32_t*)(g_x2ph + ((size_t)bc << 10) + (h2 << 5) + (j << 1)) = p;
    } else {
        int i = (blockIdx.x - 8192) * 256 + threadIdx.x;   // 98304 total
        if (i < 32768)      g_Wkh[i] = __float2bfloat16(Wk[i]);
        else if (i < 65536) g_Wvh[i - 32768] = __float2bfloat16(Wv[i - 32768]);
        else if (i < 81920) g_Wqh[i - 65536] = __float2bfloat16(Wq[i - 65536]);
        else                g_Woh[i - 81920] = __float2bfloat16(Wo[i - 81920]);
    }
}

// ---------------- kernel B: K/V projection, 2-stage cp.async pipeline ----------------
__global__ __launch_bounds__(256) void kvproj_kernel(
        const float* __restrict__ bk, const float* __restrict__ bv) {
    __shared__ __align__(16) char smem[49152];  // sX[2][8K] sWk[2][8K] sWv[2][8K]
    const uint32_t s_u = (uint32_t)__cvta_generic_to_shared(smem);

    const int b = blockIdx.y, m0 = blockIdx.x << 6;
    const int tid = threadIdx.x, wid = tid >> 5, lane = tid & 31;
    const int dw = wid & 3, mw = wid >> 2;

    float CK[4][4] = {}, CV[4][4] = {};

    auto issue = [&](int cc, int t) {
        int c0 = cc << 6;
        for (int i = tid; i < 512; i += 256) {
            int r = i >> 3, pos = i & 7;
            uint32_t dst = t * 8192 + r * 128 + ((pos ^ (r & 7)) << 4);
            cp16(s_u + dst,
                 g_x2ph + ((size_t)(b * C2 + c0 + r) << 10) + m0 + (pos << 3));
            cp16(s_u + 16384 + dst, g_Wkh + r * C2 + c0 + (pos << 3));
            cp16(s_u + 32768 + dst, g_Wvh + r * C2 + c0 + (pos << 3));
        }
        cp_commit();
    };

    issue(0, 0);
    for (int cc = 0; cc < 8; cc++) {
        int cur = cc & 1;
        cp_wait0();
        __syncthreads();
        if (cc < 7) issue(cc + 1, cur ^ 1);

        uint32_t sX_u = s_u + cur * 8192;
        uint32_t sWk_u = s_u + 16384 + cur * 8192;
        uint32_t sWv_u = s_u + 32768 + cur * 8192;
#pragma unroll
        for (int ks = 0; ks < 4; ks++) {
            int ar = (dw << 4) + (lane & 15);
            int ag = (ks << 1) + (lane >> 4);
            uint32_t aoff = ar * 128 + ((ag ^ (ar & 7)) << 4);
            uint32_t Ak[4], Av[4];
            ldsm4(Ak[0], Ak[1], Ak[2], Ak[3], sWk_u + aoff);
            ldsm4(Av[0], Av[1], Av[2], Av[3], sWv_u + aoff);
            int krow = (ks << 4) + (lane & 7) + (((lane >> 3) & 1) << 3);
#pragma unroll
            for (int nt = 0; nt < 2; nt++) {
                int ncol = (mw << 5) + (nt << 4) + ((lane >> 4) << 3);
                uint32_t b0, b1, b2, b3;
                ldsm4t(b0, b1, b2, b3,
                       sX_u + krow * 128 + (((ncol >> 3) ^ (krow & 7)) << 4));
                mma16816(CK[2 * nt], Ak, b0, b1);
                mma16816(CK[2 * nt + 1], Ak, b2, b3);
                mma16816(CV[2 * nt], Av, b0, b1);
                mma16816(CV[2 * nt + 1], Av, b2, b3);
            }
        }
    }
    int row0 = (dw << 4) + (lane >> 2);
    float bk0 = bk[row0], bk1 = bk[row0 + 8];
    float bv0 = bv[row0], bv1 = bv[row0 + 8];
    __nv_bfloat16* Kp = g_Kth + ((size_t)b * 64 + row0) * M + m0;
    __nv_bfloat16* Vp = g_Vth + ((size_t)b * 64 + row0) * M + m0;
#pragma unroll
    for (int nt = 0; nt < 2; nt++)
#pragma unroll
        for (int h = 0; h < 2; h++) {
            int ci = 2 * nt + h;
            int ncol = (mw << 5) + (nt << 4) + (h << 3) + ((lane & 3) << 1);
            // K pre-scaled by log2e so attention uses raw ex2
            *(uint32_t*)(Kp + ncol) =
                pack_bf16((CK[ci][0] + bk0) * LOG2E, (CK[ci][1] + bk0) * LOG2E);
            *(uint32_t*)(Kp + (size_t)8 * M + ncol) =
                pack_bf16((CK[ci][2] + bk1) * LOG2E, (CK[ci][3] + bk1) * LOG2E);
            *(uint32_t*)(Vp + ncol) = pack_bf16(CV[ci][0] + bv0, CV[ci][1] + bv0);
            *(uint32_t*)(Vp + (size_t)8 * M + ncol) = pack_bf16(CV[ci][2] + bv1, CV[ci][3] + bv1);
        }
}

// ---------------- kernel C: Q projection, reg-prefetch double buffer ----------------
__global__ __launch_bounds__(256) void qproj_kernel(
        const float* __restrict__ x1, const float* __restrict__ bq) {
    __shared__ __align__(16) char smem[49152];  // sW[4][8K] + sX[2][8K]
    const uint32_t s_u = (uint32_t)__cvta_generic_to_shared(smem);
    const uint32_t sXb_u = s_u + 32768;

    const int b = blockIdx.y, n0 = blockIdx.x << 6;
    const int tid = threadIdx.x, wid = tid >> 5, lane = tid & 31;
    const int dw = wid & 3, mw = wid >> 2;

    // all Wq chunks -> smem once
    for (int i = tid; i < 2048; i += 256) {
        int ch = i >> 9, j = i & 511, r = j >> 3, pos = j & 7;
        cp16(s_u + ch * 8192 + r * 128 + ((pos ^ (r & 7)) << 4),
             g_Wqh + r * C1 + (ch << 6) + (pos << 3));
    }
    cp_commit();

    const int r0 = tid >> 4, p4 = tid & 15;
    const float* xbase = x1 + ((size_t)(b * C1) << 12) + n0 + (p4 << 2);
    float4 f[4];
#pragma unroll
    for (int k = 0; k < 4; k++)
        f[k] = *(const float4*)(xbase + ((size_t)(r0 + 16 * k) << 12));

    float C[4][4] = {};
    const int r7 = r0 & 7;
    const uint32_t sphys = r0 * 128 + (((p4 >> 1) ^ r7) << 4) + ((p4 & 1) << 3);

    for (int cc = 0; cc < 4; cc++) {
        int cur = cc & 1;
        char* xb = smem + 32768 + cur * 8192;
#pragma unroll
        for (int k = 0; k < 4; k++)
            *(uint2*)(xb + sphys + k * 2048) =
                make_uint2(pack_bf16(f[k].x, f[k].y), pack_bf16(f[k].z, f[k].w));
        if (cc < 3) {
            float4 f2[4];
#pragma unroll
            for (int k = 0; k < 4; k++)
                f2[k] = *(const float4*)(xbase +
                         ((size_t)(((cc + 1) << 6) + r0 + 16 * k) << 12));
            if (cc == 0) cp_wait0();
            __syncthreads();

            uint32_t sW_u = s_u + cc * 8192;
            uint32_t sX_u = sXb_u + cur * 8192;
#pragma unroll
            for (int ks = 0; ks < 4; ks++) {
                int ar = (dw << 4) + (lane & 15);
                int ag = (ks << 1) + (lane >> 4);
                uint32_t A[4];
                ldsm4(A[0], A[1], A[2], A[3], sW_u + ar * 128 + ((ag ^ (ar & 7)) << 4));
                int krow = (ks << 4) + (lane & 7) + (((lane >> 3) & 1) << 3);
#pragma unroll
                for (int nt = 0; nt < 2; nt++) {
                    int ncol = (mw << 5) + (nt << 4) + ((lane >> 4) << 3);
                    uint32_t b0, b1, b2, b3;
                    ldsm4t(b0, b1, b2, b3,
                           sX_u + krow * 128 + (((ncol >> 3) ^ (krow & 7)) << 4));
                    mma16816(C[2 * nt], A, b0, b1);
                    mma16816(C[2 * nt + 1], A, b2, b3);
                }
            }
#pragma unroll
            for (int k = 0; k < 4; k++) f[k] = f2[k];
        } else {
            __syncthreads();
            uint32_t sW_u = s_u + cc * 8192;
            uint32_t sX_u = sXb_u + cur * 8192;
#pragma unroll
            for (int ks = 0; ks < 4; ks++) {
                int ar = (dw << 4) + (lane & 15);
                int ag = (ks << 1) + (lane >> 4);
                uint32_t A[4];
                ldsm4(A[0], A[1], A[2], A[3], sW_u + ar * 128 + ((ag ^ (ar & 7)) << 4));
                int krow = (ks << 4) + (lane & 7) + (((lane >> 3) & 1) << 3);
#pragma unroll
                for (int nt = 0; nt < 2; nt++) {
                    int ncol = (mw << 5) + (nt << 4) + ((lane >> 4) << 3);
                    uint32_t b0, b1, b2, b3;
                    ldsm4t(b0, b1, b2, b3,
                           sX_u + krow * 128 + (((ncol >> 3) ^ (krow & 7)) << 4));
                    mma16816(C[2 * nt], A, b0, b1);
                    mma16816(C[2 * nt + 1], A, b2, b3);
                }
            }
        }
    }
    int row0 = (dw << 4) + (lane >> 2);
    float b0v = bq[row0], b1v = bq[row0 + 8];
    __nv_bfloat16* Qp = g_Qth + ((size_t)b * 64 + row0) * HW + n0;
#pragma unroll
    for (int nt = 0; nt < 2; nt++)
#pragma unroll
        for (int h = 0; h < 2; h++) {
            int ci = 2 * nt + h;
            int ncol = (mw << 5) + (nt << 4) + (h << 3) + ((lane & 3) << 1);
            *(uint32_t*)(Qp + ncol) = pack_bf16(C[ci][0] + b0v, C[ci][1] + b0v);
            *(uint32_t*)(Qp + (size_t)8 * HW + ncol) = pack_bf16(C[ci][2] + b1v, C[ci][3] + b1v);
        }
}

// ---------------- kernel D: attention + out-proj + residual ----------------
__global__ __launch_bounds__(256, 2) void attn_kernel(
        const float* __restrict__ x1, const float* __restrict__ bo,
        float* __restrict__ out) {
    extern __shared__ char sm[];
    float* sY = (float*)(sm + 32768);

    const int b = blockIdx.y, n0 = blockIdx.x << 7;
    const int tid = threadIdx.x, wid = tid >> 5, lane = tid & 31;
    const uint32_t sm_u = (uint32_t)__cvta_generic_to_shared(sm);

    const __nv_bfloat16* Qg = g_Qth + (size_t)b * 64 * HW + n0;
    const __nv_bfloat16* Kg0 = g_Kth + (size_t)b * 64 * M;
    const __nv_bfloat16* Vg0 = g_Vth + (size_t)b * 64 * M;

    for (int i = tid; i < 1024; i += 256) {
        int r = i >> 4, pos = i & 15;
        cp16(sm_u + r * 256 + ((pos ^ (r & 7)) << 4), Qg + (size_t)r * HW + (pos << 3));
    }
    for (int i = tid; i < 512; i += 256) {
        int r = i >> 3, pos = i & 7;
        uint32_t sw = ((pos ^ (r & 7)) << 4);
        cp16(sm_u + 16384 + r * 128 + sw, Kg0 + (size_t)r * M + (pos << 3));
        cp16(sm_u + 24576 + r * 128 + sw, Vg0 + (size_t)r * M + (pos << 3));
    }
    cp_commit(); cp_wait0();
    __syncthreads();

    uint32_t Qf[4][4];
    {
        int mcol = (wid << 4) + (((lane >> 3) & 1) << 3);
#pragma unroll
        for (int s = 0; s < 4; s++) {
            int krow = (s << 4) + (lane & 7) + ((lane >> 4) << 3);
            ldsm4t(Qf[s][0], Qf[s][1], Qf[s][2], Qf[s][3],
                   sm_u + krow * 256 + (((mcol >> 3) ^ (krow & 7)) << 4));
        }
    }
    __syncthreads();

    float O[8][4] = {};
    float l0 = 0.f, l1 = 0.f;

    const int brow = (lane & 7) + ((lane >> 4) << 3);
    const int bgsel = (lane >> 3) & 1;
    const int tkrow = (lane & 7) + (((lane >> 3) & 1) << 3);
    const int tnsel = (lane >> 4) << 3;

    for (int kt = 0; kt < 16; kt++) {
        uint32_t cbase = sm_u + (((kt & 1) ^ 1) << 14);
        if (kt < 15) {
            uint32_t pb = sm_u + ((kt & 1) << 14);
            const __nv_bfloat16* Kg = Kg0 + (kt + 1) * 64;
            const __nv_bfloat16* Vg = Vg0 + (kt + 1) * 64;
            for (int i = tid; i < 512; i += 256) {
                int r = i >> 3, pos = i & 7;
                uint32_t sw = ((pos ^ (r & 7)) << 4);
                cp16(pb + r * 128 + sw, Kg + (size_t)r * M + (pos << 3));
                cp16(pb + 8192 + r * 128 + sw, Vg + (size_t)r * M + (pos << 3));
            }
        } else {
            for (int i = tid; i < 1024; i += 256) {
                int r = 128 + (i >> 3), pos = i & 7;
                cp16(sm_u + r * 128 + ((pos ^ (r & 7)) << 4), g_Woh + r * 64 + (pos << 3));
            }
        }
        cp_commit();

        float S[8][4] = {};
#pragma unroll
        for (int s = 0; s < 4; s++) {
            int krow = (s << 4) + tkrow;
            uint32_t rb = cbase + krow * 128;
            int r7x = (krow & 7);
#pragma unroll
            for (int nh = 0; nh < 4; nh++) {
                int ncol = (nh << 4) + tnsel;
                uint32_t b0, b1, b2, b3;
                ldsm4t(b0, b1, b2, b3, rb + (((ncol >> 3) ^ r7x) << 4));
                mma16816(S[2 * nh], Qf[s], b0, b1);
                mma16816(S[2 * nh + 1], Qf[s], b2, b3);
            }
        }
        uint32_t Pf[4][4];
#pragma unroll
        for (int nt = 0; nt < 8; nt++) {
#pragma unroll
            for (int j = 0; j < 4; j++) S[nt][j] = ex2f(S[nt][j]);  // K pre-scaled by log2e
            l0 += S[nt][0] + S[nt][1];
            l1 += S[nt][2] + S[nt][3];
        }
#pragma unroll
        for (int kk = 0; kk < 4; kk++) {
            Pf[kk][0] = pack_bf16(S[2 * kk][0], S[2 * kk][1]);
            Pf[kk][1] = pack_bf16(S[2 * kk][2], S[2 * kk][3]);
            Pf[kk][2] = pack_bf16(S[2 * kk + 1][0], S[2 * kk + 1][1]);
            Pf[kk][3] = pack_bf16(S[2 * kk + 1][2], S[2 * kk + 1][3]);
        }
        uint32_t vbase = cbase + 8192;
#pragma unroll
        for (int kk = 0; kk < 4; kk++) {
#pragma unroll
            for (int dh = 0; dh < 4; dh++) {
                int r = (dh << 4) + brow;
                int g = (kk << 1) + bgsel;
                uint32_t b0, b1, b2, b3;
                ldsm4(b0, b1, b2, b3, vbase + r * 128 + ((g ^ (r & 7)) << 4));
                mma16816(O[2 * dh], Pf[kk], b0, b1);
                mma16816(O[2 * dh + 1], Pf[kk], b2, b3);
            }
        }
        cp_wait0();
        __syncthreads();
    }

    l0 += __shfl_xor_sync(0xffffffffu, l0, 1);
    l0 += __shfl_xor_sync(0xffffffffu, l0, 2);
    l1 += __shfl_xor_sync(0xffffffffu, l1, 1);
    l1 += __shfl_xor_sync(0xffffffffu, l1, 2);
    float inv0 = 1.0f / l0, inv1 = 1.0f / l1;
    uint32_t Of[4][4];
#pragma unroll
    for (int s = 0; s < 4; s++) {
        Of[s][0] = pack_bf16(O[2 * s][0] * inv0, O[2 * s][1] * inv0);
        Of[s][1] = pack_bf16(O[2 * s][2] * inv1, O[2 * s][3] * inv1);
        Of[s][2] = pack_bf16(O[2 * s + 1][0] * inv0, O[2 * s + 1][1] * inv0);
        Of[s][3] = pack_bf16(O[2 * s + 1][2] * inv1, O[2 * s + 1][3] * inv1);
    }

    for (int i = tid; i < 1024; i += 256) {
        int r = i >> 3, pos = i & 7;
        cp16(sm_u + r * 128 + ((pos ^ (r & 7)) << 4), g_Woh + r * 64 + (pos << 3));
    }
    cp_commit(); cp_wait0();
    __syncthreads();

    const size_t xoff = (size_t)b * (C1 * HW) + n0;
    const int qrow = (wid << 4) + (lane >> 2);
    for (int cc = 0; cc < 4; cc++) {
        float Y[8][4] = {};
#pragma unroll
        for (int s = 0; s < 4; s++) {
#pragma unroll
            for (int ch = 0; ch < 4; ch++) {
                int r = (cc << 6) + (ch << 4) + brow;
                int g = (s << 1) + bgsel;
                uint32_t b0, b1, b2, b3;
                ldsm4(b0, b1, b2, b3, sm_u + r * 128 + ((g ^ (r & 7)) << 4));
                mma16816(Y[2 * ch], Of[s], b0, b1);
                mma16816(Y[2 * ch + 1], Of[s], b2, b3);
            }
        }
        if (cc) __syncthreads();
#pragma unroll
        for (int nt = 0; nt < 8; nt++) {
            int c = (nt << 3) + ((lane & 3) << 1);
            sY[c * LDY + qrow] = Y[nt][0];
            sY[(c + 1) * LDY + qrow] = Y[nt][1];
            sY[c * LDY + qrow + 8] = Y[nt][2];
            sY[(c + 1) * LDY + qrow + 8] = Y[nt][3];
        }
        __syncthreads();
        for (int i2 = tid; i2 < 8192; i2 += 256) {
            int c = i2 >> 7, q = i2 & 127;
            size_t gaddr = xoff + (size_t)((cc << 6) + c) * HW + q;
            out[gaddr] = x1[gaddr] + sY[c * LDY + q] + bo[(cc << 6) + c];
        }
    }
}

extern "C" void kernel_launch(void* const* d_in, const int* in_sizes, int n_in,
                              void* d_out, int out_size) {
    const float* x1 = (const float*)d_in[0];
    const float* x2 = (const float*)d_in[1];
    const float* Wq = (const float*)d_in[2];
    const float* bq = (const float*)d_in[3];
    const float* Wk = (const float*)d_in[4];
    const float* bk = (const float*)d_in[5];
    const float* Wv = (const float*)d_in[6];
    const float* bv = (const float*)d_in[7];
    const float* Wo = (const float*)d_in[8];
    const float* bo = (const float*)d_in[9];
    float* out = (float*)d_out;
    (void)in_sizes; (void)n_in; (void)out_size;

    static const int smem_attn = 32768 + 64 * LDY * 4;
    cudaFuncSetAttribute(attn_kernel, cudaFuncAttributeMaxDynamicSharedMemorySize,
                         smem_attn);

    prep_kernel<<<8192 + 384, 256>>>(x2, Wk, Wv, Wq, Wo);
    kvproj_kernel<<<dim3(M / 64, NB), 256>>>(bk, bv);
    qproj_kernel<<<dim3(HW / 64, NB), 256>>>(x1, bq);
    attn_kernel<<<dim3(HW / 128, NB), 256, smem_attn>>>(x1, bo, out);
}

// round 7
// speedup vs baseline: 7.4858x; 1.1223x over previous
#include <cuda_runtime.h>
#include <cuda_bf16.h>
#include <cstdint>

#define NB 8
#define C1 256
#define C2 512
#define HW 4096
#define D  64
#define M  1024
#define LDY 132
#define LOG2E 1.4426950408889634f

// Scratch (device globals: allocation-free rule)
__device__ __align__(16) __nv_bfloat16 g_x2ph[NB * C2 * M];  // pooled x2, bf16
__device__ __align__(16) __nv_bfloat16 g_Qth[NB * D * HW];   // [b][d][n]
__device__ __align__(16) __nv_bfloat16 g_Kth[NB * D * M];    // [b][d][m], pre-scaled by log2e
__device__ __align__(16) __nv_bfloat16 g_Vth[NB * D * M];    // [b][d][m]
__device__ __align__(16) __nv_bfloat16 g_Wkh[D * C2];
__device__ __align__(16) __nv_bfloat16 g_Wvh[D * C2];
__device__ __align__(16) __nv_bfloat16 g_Wqh[D * C1];
__device__ __align__(16) __nv_bfloat16 g_Woh[C1 * D];

__device__ __forceinline__ uint32_t pack_bf16(float a, float b) {
    __nv_bfloat162 h = __floats2bfloat162_rn(a, b);
    return *reinterpret_cast<uint32_t*>(&h);
}
__device__ __forceinline__ float ex2f(float x) {
    float y;
    asm("ex2.approx.f32 %0, %1;" : "=f"(y) : "f"(x));
    return y;
}
__device__ __forceinline__ void ldsm4(uint32_t& r0, uint32_t& r1, uint32_t& r2,
                                      uint32_t& r3, uint32_t addr) {
    asm volatile("ldmatrix.sync.aligned.m8n8.x4.shared.b16 {%0,%1,%2,%3}, [%4];\n"
                 : "=r"(r0), "=r"(r1), "=r"(r2), "=r"(r3) : "r"(addr));
}
__device__ __forceinline__ void ldsm4t(uint32_t& r0, uint32_t& r1, uint32_t& r2,
                                       uint32_t& r3, uint32_t addr) {
    asm volatile("ldmatrix.sync.aligned.m8n8.x4.trans.shared.b16 {%0,%1,%2,%3}, [%4];\n"
                 : "=r"(r0), "=r"(r1), "=r"(r2), "=r"(r3) : "r"(addr));
}
__device__ __forceinline__ void mma16816(float c[4], const uint32_t a[4],
                                         uint32_t b0, uint32_t b1) {
    asm volatile("mma.sync.aligned.m16n8k16.row.col.f32.bf16.bf16.f32 "
                 "{%0,%1,%2,%3}, {%4,%5,%6,%7}, {%8,%9}, {%0,%1,%2,%3};\n"
                 : "+f"(c[0]), "+f"(c[1]), "+f"(c[2]), "+f"(c[3])
                 : "r"(a[0]), "r"(a[1]), "r"(a[2]), "r"(a[3]), "r"(b0), "r"(b1));
}
__device__ __forceinline__ void cp16(uint32_t saddr, const void* g) {
    asm volatile("cp.async.cg.shared.global [%0], [%1], 16;\n" :: "r"(saddr), "l"(g));
}
__device__ __forceinline__ void cp_commit() { asm volatile("cp.async.commit_group;\n"); }
__device__ __forceinline__ void cp_wait0() { asm volatile("cp.async.wait_group 0;\n"); }

// ---------------- kernel A: pool (blocks < 8192) + weight cvt (rest) ----------------
__global__ void prep_kernel(const float* __restrict__ x2,
                            const float* __restrict__ Wk, const float* __restrict__ Wv,
                            const float* __restrict__ Wq, const float* __restrict__ Wo) {
    if (blockIdx.x < 8192) {
        int i = blockIdx.x * 256 + threadIdx.x;
        int j = i & 15, h2 = (i >> 4) & 31, bc = i >> 9;
        const float* s = x2 + ((size_t)bc << 12) + (h2 << 7) + (j << 2);
        float4 f0 = *(const float4*)s;
        float4 f1 = *(const float4*)(s + 64);
        uint32_t p = pack_bf16(0.25f * (f0.x + f0.y + f1.x + f1.y),
                               0.25f * (f0.z + f0.w + f1.z + f1.w));
        *(uint32_t*)(g_x2ph + ((size_t)bc << 10) + (h2 << 5) + (j << 1)) = p;
    } else {
        int i = (blockIdx.x - 8192) * 256 + threadIdx.x;   // 98304 total
        if (i < 32768)      g_Wkh[i] = __float2bfloat16(Wk[i]);
        else if (i < 65536) g_Wvh[i - 32768] = __float2bfloat16(Wv[i - 32768]);
        else if (i < 81920) g_Wqh[i - 65536] = __float2bfloat16(Wq[i - 65536]);
        else                g_Woh[i - 81920] = __float2bfloat16(Wo[i - 81920]);
    }
}

// ---------------- kernel B: K/V projection, 2-stage cp.async pipeline ----------------
__global__ __launch_bounds__(256) void kvproj_kernel(
        const float* __restrict__ bk, const float* __restrict__ bv) {
    __shared__ __align__(16) char smem[49152];  // sX[2][8K] sWk[2][8K] sWv[2][8K]
    const uint32_t s_u = (uint32_t)__cvta_generic_to_shared(smem);

    const int b = blockIdx.y, m0 = blockIdx.x << 6;
    const int tid = threadIdx.x, wid = tid >> 5, lane = tid & 31;
    const int dw = wid & 3, mw = wid >> 2;

    float CK[4][4] = {}, CV[4][4] = {};

    auto issue = [&](int cc, int t) {
        int c0 = cc << 6;
        for (int i = tid; i < 512; i += 256) {
            int r = i >> 3, pos = i & 7;
            uint32_t dst = t * 8192 + r * 128 + ((pos ^ (r & 7)) << 4);
            cp16(s_u + dst,
                 g_x2ph + ((size_t)(b * C2 + c0 + r) << 10) + m0 + (pos << 3));
            cp16(s_u + 16384 + dst, g_Wkh + r * C2 + c0 + (pos << 3));
            cp16(s_u + 32768 + dst, g_Wvh + r * C2 + c0 + (pos << 3));
        }
        cp_commit();
    };

    issue(0, 0);
    for (int cc = 0; cc < 8; cc++) {
        int cur = cc & 1;
        cp_wait0();
        __syncthreads();
        if (cc < 7) issue(cc + 1, cur ^ 1);

        uint32_t sX_u = s_u + cur * 8192;
        uint32_t sWk_u = s_u + 16384 + cur * 8192;
        uint32_t sWv_u = s_u + 32768 + cur * 8192;
#pragma unroll
        for (int ks = 0; ks < 4; ks++) {
            int ar = (dw << 4) + (lane & 15);
            int ag = (ks << 1) + (lane >> 4);
            uint32_t aoff = ar * 128 + ((ag ^ (ar & 7)) << 4);
            uint32_t Ak[4], Av[4];
            ldsm4(Ak[0], Ak[1], Ak[2], Ak[3], sWk_u + aoff);
            ldsm4(Av[0], Av[1], Av[2], Av[3], sWv_u + aoff);
            int krow = (ks << 4) + (lane & 7) + (((lane >> 3) & 1) << 3);
#pragma unroll
            for (int nt = 0; nt < 2; nt++) {
                int ncol = (mw << 5) + (nt << 4) + ((lane >> 4) << 3);
                uint32_t b0, b1, b2, b3;
                ldsm4t(b0, b1, b2, b3,
                       sX_u + krow * 128 + (((ncol >> 3) ^ (krow & 7)) << 4));
                mma16816(CK[2 * nt], Ak, b0, b1);
                mma16816(CK[2 * nt + 1], Ak, b2, b3);
                mma16816(CV[2 * nt], Av, b0, b1);
                mma16816(CV[2 * nt + 1], Av, b2, b3);
            }
        }
    }
    int row0 = (dw << 4) + (lane >> 2);
    float bk0 = bk[row0], bk1 = bk[row0 + 8];
    float bv0 = bv[row0], bv1 = bv[row0 + 8];
    __nv_bfloat16* Kp = g_Kth + ((size_t)b * 64 + row0) * M + m0;
    __nv_bfloat16* Vp = g_Vth + ((size_t)b * 64 + row0) * M + m0;
#pragma unroll
    for (int nt = 0; nt < 2; nt++)
#pragma unroll
        for (int h = 0; h < 2; h++) {
            int ci = 2 * nt + h;
            int ncol = (mw << 5) + (nt << 4) + (h << 3) + ((lane & 3) << 1);
            // K pre-scaled by log2e so attention uses raw ex2
            *(uint32_t*)(Kp + ncol) =
                pack_bf16((CK[ci][0] + bk0) * LOG2E, (CK[ci][1] + bk0) * LOG2E);
            *(uint32_t*)(Kp + (size_t)8 * M + ncol) =
                pack_bf16((CK[ci][2] + bk1) * LOG2E, (CK[ci][3] + bk1) * LOG2E);
            *(uint32_t*)(Vp + ncol) = pack_bf16(CV[ci][0] + bv0, CV[ci][1] + bv0);
            *(uint32_t*)(Vp + (size_t)8 * M + ncol) = pack_bf16(CV[ci][2] + bv1, CV[ci][3] + bv1);
        }
}

// ---------------- kernel C: Q projection, reg-prefetch double buffer ----------------
__global__ __launch_bounds__(256) void qproj_kernel(
        const float* __restrict__ x1, const float* __restrict__ bq) {
    __shared__ __align__(16) char smem[49152];  // sW[4][8K] + sX[2][8K]
    const uint32_t s_u = (uint32_t)__cvta_generic_to_shared(smem);
    const uint32_t sXb_u = s_u + 32768;

    const int b = blockIdx.y, n0 = blockIdx.x << 6;
    const int tid = threadIdx.x, wid = tid >> 5, lane = tid & 31;
    const int dw = wid & 3, mw = wid >> 2;

    for (int i = tid; i < 2048; i += 256) {
        int ch = i >> 9, j = i & 511, r = j >> 3, pos = j & 7;
        cp16(s_u + ch * 8192 + r * 128 + ((pos ^ (r & 7)) << 4),
             g_Wqh + r * C1 + (ch << 6) + (pos << 3));
    }
    cp_commit();

    const int r0 = tid >> 4, p4 = tid & 15;
    const float* xbase = x1 + ((size_t)(b * C1) << 12) + n0 + (p4 << 2);
    float4 f[4];
#pragma unroll
    for (int k = 0; k < 4; k++)
        f[k] = *(const float4*)(xbase + ((size_t)(r0 + 16 * k) << 12));

    float C[4][4] = {};
    const int r7 = r0 & 7;
    const uint32_t sphys = r0 * 128 + (((p4 >> 1) ^ r7) << 4) + ((p4 & 1) << 3);

    for (int cc = 0; cc < 4; cc++) {
        int cur = cc & 1;
        char* xb = smem + 32768 + cur * 8192;
#pragma unroll
        for (int k = 0; k < 4; k++)
            *(uint2*)(xb + sphys + k * 2048) =
                make_uint2(pack_bf16(f[k].x, f[k].y), pack_bf16(f[k].z, f[k].w));
        float4 f2[4];
        if (cc < 3) {
#pragma unroll
            for (int k = 0; k < 4; k++)
                f2[k] = *(const float4*)(xbase +
                         ((size_t)(((cc + 1) << 6) + r0 + 16 * k) << 12));
        }
        if (cc == 0) cp_wait0();
        __syncthreads();

        uint32_t sW_u = s_u + cc * 8192;
        uint32_t sX_u = sXb_u + cur * 8192;
#pragma unroll
        for (int ks = 0; ks < 4; ks++) {
            int ar = (dw << 4) + (lane & 15);
            int ag = (ks << 1) + (lane >> 4);
            uint32_t A[4];
            ldsm4(A[0], A[1], A[2], A[3], sW_u + ar * 128 + ((ag ^ (ar & 7)) << 4));
            int krow = (ks << 4) + (lane & 7) + (((lane >> 3) & 1) << 3);
#pragma unroll
            for (int nt = 0; nt < 2; nt++) {
                int ncol = (mw << 5) + (nt << 4) + ((lane >> 4) << 3);
                uint32_t b0, b1, b2, b3;
                ldsm4t(b0, b1, b2, b3,
                       sX_u + krow * 128 + (((ncol >> 3) ^ (krow & 7)) << 4));
                mma16816(C[2 * nt], A, b0, b1);
                mma16816(C[2 * nt + 1], A, b2, b3);
            }
        }
        if (cc < 3) {
#pragma unroll
            for (int k = 0; k < 4; k++) f[k] = f2[k];
        }
    }
    int row0 = (dw << 4) + (lane >> 2);
    float b0v = bq[row0], b1v = bq[row0 + 8];
    __nv_bfloat16* Qp = g_Qth + ((size_t)b * 64 + row0) * HW + n0;
#pragma unroll
    for (int nt = 0; nt < 2; nt++)
#pragma unroll
        for (int h = 0; h < 2; h++) {
            int ci = 2 * nt + h;
            int ncol = (mw << 5) + (nt << 4) + (h << 3) + ((lane & 3) << 1);
            *(uint32_t*)(Qp + ncol) = pack_bf16(C[ci][0] + b0v, C[ci][1] + b0v);
            *(uint32_t*)(Qp + (size_t)8 * HW + ncol) = pack_bf16(C[ci][2] + b1v, C[ci][3] + b1v);
        }
}

// ---------------- kernel D: attention + out-proj + residual ----------------
// CTA: 128 queries, 4 warps, warp = 32 queries (two m16 fragments share B frags).
__global__ __launch_bounds__(128, 2) void attn_kernel(
        const float* __restrict__ x1, const float* __restrict__ bo,
        float* __restrict__ out) {
    extern __shared__ char sm[];
    float* sY = (float*)(sm + 32768);

    const int b = blockIdx.y, n0 = blockIdx.x << 7;
    const int tid = threadIdx.x, wid = tid >> 5, lane = tid & 31;
    const uint32_t sm_u = (uint32_t)__cvta_generic_to_shared(sm);

    const __nv_bfloat16* Qg = g_Qth + (size_t)b * 64 * HW + n0;
    const __nv_bfloat16* Kg0 = g_Kth + (size_t)b * 64 * M;
    const __nv_bfloat16* Vg0 = g_Vth + (size_t)b * 64 * M;

    // stage Qt [64][128] into sm[0,16K) + K/V tile 0 into B1
    for (int i = tid; i < 1024; i += 128) {
        int r = i >> 4, pos = i & 15;
        cp16(sm_u + r * 256 + ((pos ^ (r & 7)) << 4), Qg + (size_t)r * HW + (pos << 3));
    }
    for (int i = tid; i < 512; i += 128) {
        int r = i >> 3, pos = i & 7;
        uint32_t sw = ((pos ^ (r & 7)) << 4);
        cp16(sm_u + 16384 + r * 128 + sw, Kg0 + (size_t)r * M + (pos << 3));
        cp16(sm_u + 24576 + r * 128 + sw, Vg0 + (size_t)r * M + (pos << 3));
    }
    cp_commit(); cp_wait0();
    __syncthreads();

    // Q fragments: two m16 blocks per warp, 4 k-steps each
    uint32_t Qf[2][4][4];
#pragma unroll
    for (int h = 0; h < 2; h++) {
        int mcol = (wid << 5) + (h << 4) + (((lane >> 3) & 1) << 3);
#pragma unroll
        for (int s = 0; s < 4; s++) {
            int krow = (s << 4) + (lane & 7) + ((lane >> 4) << 3);
            ldsm4t(Qf[h][s][0], Qf[h][s][1], Qf[h][s][2], Qf[h][s][3],
                   sm_u + krow * 256 + (((mcol >> 3) ^ (krow & 7)) << 4));
        }
    }
    __syncthreads();   // sm[0,16K) -> buffer B0

    float O[2][8][4] = {};
    float l0[2] = {}, l1[2] = {};

    const int brow = (lane & 7) + ((lane >> 4) << 3);
    const int bgsel = (lane >> 3) & 1;
    const int tkrow = (lane & 7) + (((lane >> 3) & 1) << 3);
    const int tnsel = (lane >> 4) << 3;

    for (int kt = 0; kt < 16; kt++) {
        uint32_t cbase = sm_u + (((kt & 1) ^ 1) << 14);
        if (kt < 15) {
            uint32_t pb = sm_u + ((kt & 1) << 14);
            const __nv_bfloat16* Kg = Kg0 + (kt + 1) * 64;
            const __nv_bfloat16* Vg = Vg0 + (kt + 1) * 64;
            for (int i = tid; i < 512; i += 128) {
                int r = i >> 3, pos = i & 7;
                uint32_t sw = ((pos ^ (r & 7)) << 4);
                cp16(pb + r * 128 + sw, Kg + (size_t)r * M + (pos << 3));
                cp16(pb + 8192 + r * 128 + sw, Vg + (size_t)r * M + (pos << 3));
            }
        } else {
            // kt==15 computes on B0; B1 free -> Wo rows 128..255
            for (int i = tid; i < 1024; i += 128) {
                int r = 128 + (i >> 3), pos = i & 7;
                cp16(sm_u + r * 128 + ((pos ^ (r & 7)) << 4), g_Woh + r * 64 + (pos << 3));
            }
        }
        cp_commit();

        // S = Q K^T  (each K fragment feeds both m16 blocks)
        float S[2][8][4] = {};
#pragma unroll
        for (int s = 0; s < 4; s++) {
            int krow = (s << 4) + tkrow;
            uint32_t rb = cbase + krow * 128;
            int r7x = (krow & 7);
#pragma unroll
            for (int nh = 0; nh < 4; nh++) {
                int ncol = (nh << 4) + tnsel;
                uint32_t b0, b1, b2, b3;
                ldsm4t(b0, b1, b2, b3, rb + (((ncol >> 3) ^ r7x) << 4));
#pragma unroll
                for (int h = 0; h < 2; h++) {
                    mma16816(S[h][2 * nh], Qf[h][s], b0, b1);
                    mma16816(S[h][2 * nh + 1], Qf[h][s], b2, b3);
                }
            }
        }
        // softmax numerator + pack
        uint32_t Pf[2][4][4];
#pragma unroll
        for (int h = 0; h < 2; h++) {
#pragma unroll
            for (int nt = 0; nt < 8; nt++) {
#pragma unroll
                for (int j = 0; j < 4; j++) S[h][nt][j] = ex2f(S[h][nt][j]);
                l0[h] += S[h][nt][0] + S[h][nt][1];
                l1[h] += S[h][nt][2] + S[h][nt][3];
            }
#pragma unroll
            for (int kk = 0; kk < 4; kk++) {
                Pf[h][kk][0] = pack_bf16(S[h][2 * kk][0], S[h][2 * kk][1]);
                Pf[h][kk][1] = pack_bf16(S[h][2 * kk][2], S[h][2 * kk][3]);
                Pf[h][kk][2] = pack_bf16(S[h][2 * kk + 1][0], S[h][2 * kk + 1][1]);
                Pf[h][kk][3] = pack_bf16(S[h][2 * kk + 1][2], S[h][2 * kk + 1][3]);
            }
        }
        // O += P V
        uint32_t vbase = cbase + 8192;
#pragma unroll
        for (int kk = 0; kk < 4; kk++) {
#pragma unroll
            for (int dh = 0; dh < 4; dh++) {
                int r = (dh << 4) + brow;
                int g = (kk << 1) + bgsel;
                uint32_t b0, b1, b2, b3;
                ldsm4(b0, b1, b2, b3, vbase + r * 128 + ((g ^ (r & 7)) << 4));
#pragma unroll
                for (int h = 0; h < 2; h++) {
                    mma16816(O[h][2 * dh], Pf[h][kk], b0, b1);
                    mma16816(O[h][2 * dh + 1], Pf[h][kk], b2, b3);
                }
            }
        }
        cp_wait0();
        __syncthreads();
    }

    // normalize, build O fragments
    uint32_t Of[2][4][4];
#pragma unroll
    for (int h = 0; h < 2; h++) {
        float a0 = l0[h], a1 = l1[h];
        a0 += __shfl_xor_sync(0xffffffffu, a0, 1);
        a0 += __shfl_xor_sync(0xffffffffu, a0, 2);
        a1 += __shfl_xor_sync(0xffffffffu, a1, 1);
        a1 += __shfl_xor_sync(0xffffffffu, a1, 2);
        float inv0 = 1.0f / a0, inv1 = 1.0f / a1;
#pragma unroll
        for (int s = 0; s < 4; s++) {
            Of[h][s][0] = pack_bf16(O[h][2 * s][0] * inv0, O[h][2 * s][1] * inv0);
            Of[h][s][1] = pack_bf16(O[h][2 * s][2] * inv1, O[h][2 * s][3] * inv1);
            Of[h][s][2] = pack_bf16(O[h][2 * s + 1][0] * inv0, O[h][2 * s + 1][1] * inv0);
            Of[h][s][3] = pack_bf16(O[h][2 * s + 1][2] * inv1, O[h][2 * s + 1][3] * inv1);
        }
    }

    // stage Wo rows 0..127 into B0 (upper half already in B1)
    for (int i = tid; i < 1024; i += 128) {
        int r = i >> 3, pos = i & 7;
        cp16(sm_u + r * 128 + ((pos ^ (r & 7)) << 4), g_Woh + r * 64 + (pos << 3));
    }
    cp_commit(); cp_wait0();
    __syncthreads();

    const size_t xoff = (size_t)b * (C1 * HW) + n0;
    for (int cc = 0; cc < 4; cc++) {
        float Y[2][8][4] = {};
#pragma unroll
        for (int s = 0; s < 4; s++) {
#pragma unroll
            for (int ch = 0; ch < 4; ch++) {
                int r = (cc << 6) + (ch << 4) + brow;
                int g = (s << 1) + bgsel;
                uint32_t b0, b1, b2, b3;
                ldsm4(b0, b1, b2, b3, sm_u + r * 128 + ((g ^ (r & 7)) << 4));
#pragma unroll
                for (int h = 0; h < 2; h++) {
                    mma16816(Y[h][2 * ch], Of[h][s], b0, b1);
                    mma16816(Y[h][2 * ch + 1], Of[h][s], b2, b3);
                }
            }
        }
        if (cc) __syncthreads();
#pragma unroll
        for (int h = 0; h < 2; h++) {
            int qrow = (wid << 5) + (h << 4) + (lane >> 2);
#pragma unroll
            for (int nt = 0; nt < 8; nt++) {
                int c = (nt << 3) + ((lane & 3) << 1);
                sY[c * LDY + qrow] = Y[h][nt][0];
                sY[(c + 1) * LDY + qrow] = Y[h][nt][1];
                sY[c * LDY + qrow + 8] = Y[h][nt][2];
                sY[(c + 1) * LDY + qrow + 8] = Y[h][nt][3];
            }
        }
        __syncthreads();
        // residual + bias, float4 vectorized
        for (int i2 = tid; i2 < 2048; i2 += 128) {
            int c = i2 >> 5, q4 = (i2 & 31) << 2;
            size_t gaddr = xoff + (size_t)((cc << 6) + c) * HW + q4;
            float4 xv = *(const float4*)(x1 + gaddr);
            float4 yv = *(const float4*)&sY[c * LDY + q4];
            float bb = bo[(cc << 6) + c];
            float4 o;
            o.x = xv.x + yv.x + bb;
            o.y = xv.y + yv.y + bb;
            o.z = xv.z + yv.z + bb;
            o.w = xv.w + yv.w + bb;
            *(float4*)(out + gaddr) = o;
        }
    }
}

extern "C" void kernel_launch(void* const* d_in, const int* in_sizes, int n_in,
                              void* d_out, int out_size) {
    const float* x1 = (const float*)d_in[0];
    const float* x2 = (const float*)d_in[1];
    const float* Wq = (const float*)d_in[2];
    const float* bq = (const float*)d_in[3];
    const float* Wk = (const float*)d_in[4];
    const float* bk = (const float*)d_in[5];
    const float* Wv = (const float*)d_in[6];
    const float* bv = (const float*)d_in[7];
    const float* Wo = (const float*)d_in[8];
    const float* bo = (const float*)d_in[9];
    float* out = (float*)d_out;
    (void)in_sizes; (void)n_in; (void)out_size;

    static const int smem_attn = 32768 + 64 * LDY * 4;
    cudaFuncSetAttribute(attn_kernel, cudaFuncAttributeMaxDynamicSharedMemorySize,
                         smem_attn);

    prep_kernel<<<8192 + 384, 256>>>(x2, Wk, Wv, Wq, Wo);
    kvproj_kernel<<<dim3(M / 64, NB), 256>>>(bk, bv);
    qproj_kernel<<<dim3(HW / 64, NB), 256>>>(x1, bq);
    attn_kernel<<<dim3(HW / 128, NB), 128, smem_attn>>>(x1, bo, out);
}

// round 8
// speedup vs baseline: 7.5012x; 1.0021x over previous
#include <cuda_runtime.h>
#include <cuda_bf16.h>
#include <cstdint>

#define NB 8
#define C1 256
#define C2 512
#define HW 4096
#define D  64
#define M  1024
#define LDY 132
#define LOG2E 1.4426950408889634f

// Scratch (device globals: allocation-free rule)
__device__ __align__(16) __nv_bfloat16 g_x2ph[NB * C2 * M];  // pooled x2, bf16
__device__ __align__(16) __nv_bfloat16 g_Qth[NB * D * HW];   // [b][d][n]
__device__ __align__(16) __nv_bfloat16 g_Kth[NB * D * M];    // [b][d][m], pre-scaled by log2e
__device__ __align__(16) __nv_bfloat16 g_Vth[NB * D * M];    // [b][d][m]
__device__ __align__(16) __nv_bfloat16 g_Wkh[D * C2];
__device__ __align__(16) __nv_bfloat16 g_Wvh[D * C2];
__device__ __align__(16) __nv_bfloat16 g_Wqh[D * C1];
__device__ __align__(16) __nv_bfloat16 g_Woh[C1 * D];

__device__ __forceinline__ uint32_t pack_bf16(float a, float b) {
    __nv_bfloat162 h = __floats2bfloat162_rn(a, b);
    return *reinterpret_cast<uint32_t*>(&h);
}
__device__ __forceinline__ float ex2f(float x) {
    float y;
    asm("ex2.approx.f32 %0, %1;" : "=f"(y) : "f"(x));
    return y;
}
__device__ __forceinline__ void ldsm4(uint32_t& r0, uint32_t& r1, uint32_t& r2,
                                      uint32_t& r3, uint32_t addr) {
    asm volatile("ldmatrix.sync.aligned.m8n8.x4.shared.b16 {%0,%1,%2,%3}, [%4];\n"
                 : "=r"(r0), "=r"(r1), "=r"(r2), "=r"(r3) : "r"(addr));
}
__device__ __forceinline__ void ldsm4t(uint32_t& r0, uint32_t& r1, uint32_t& r2,
                                       uint32_t& r3, uint32_t addr) {
    asm volatile("ldmatrix.sync.aligned.m8n8.x4.trans.shared.b16 {%0,%1,%2,%3}, [%4];\n"
                 : "=r"(r0), "=r"(r1), "=r"(r2), "=r"(r3) : "r"(addr));
}
__device__ __forceinline__ void mma16816(float c[4], const uint32_t a[4],
                                         uint32_t b0, uint32_t b1) {
    asm volatile("mma.sync.aligned.m16n8k16.row.col.f32.bf16.bf16.f32 "
                 "{%0,%1,%2,%3}, {%4,%5,%6,%7}, {%8,%9}, {%0,%1,%2,%3};\n"
                 : "+f"(c[0]), "+f"(c[1]), "+f"(c[2]), "+f"(c[3])
                 : "r"(a[0]), "r"(a[1]), "r"(a[2]), "r"(a[3]), "r"(b0), "r"(b1));
}
__device__ __forceinline__ void cp16(uint32_t saddr, const void* g) {
    asm volatile("cp.async.cg.shared.global [%0], [%1], 16;\n" :: "r"(saddr), "l"(g));
}
__device__ __forceinline__ void cp_commit() { asm volatile("cp.async.commit_group;\n"); }
__device__ __forceinline__ void cp_wait0() { asm volatile("cp.async.wait_group 0;\n"); }

// ---------------- kernel A: pool (blocks < 8192) + weight cvt (rest) ----------------
__global__ void prep_kernel(const float* __restrict__ x2,
                            const float* __restrict__ Wk, const float* __restrict__ Wv,
                            const float* __restrict__ Wq, const float* __restrict__ Wo) {
    if (blockIdx.x < 8192) {
        int i = blockIdx.x * 256 + threadIdx.x;
        int j = i & 15, h2 = (i >> 4) & 31, bc = i >> 9;
        const float* s = x2 + ((size_t)bc << 12) + (h2 << 7) + (j << 2);
        float4 f0 = *(const float4*)s;
        float4 f1 = *(const float4*)(s + 64);
        uint32_t p = pack_bf16(0.25f * (f0.x + f0.y + f1.x + f1.y),
                               0.25f * (f0.z + f0.w + f1.z + f1.w));
        *(uint32_t*)(g_x2ph + ((size_t)bc << 10) + (h2 << 5) + (j << 1)) = p;
    } else {
        int i = (blockIdx.x - 8192) * 256 + threadIdx.x;   // 98304 total
        if (i < 32768)      g_Wkh[i] = __float2bfloat16(Wk[i]);
        else if (i < 65536) g_Wvh[i - 32768] = __float2bfloat16(Wv[i - 32768]);
        else if (i < 81920) g_Wqh[i - 65536] = __float2bfloat16(Wq[i - 65536]);
        else                g_Woh[i - 81920] = __float2bfloat16(Wo[i - 81920]);
    }
}

// ---------------- kernel B: K/V projection, 2-stage cp.async pipeline ----------------
__global__ __launch_bounds__(256) void kvproj_kernel(
        const float* __restrict__ bk, const float* __restrict__ bv) {
    __shared__ __align__(16) char smem[49152];  // sX[2][8K] sWk[2][8K] sWv[2][8K]
    const uint32_t s_u = (uint32_t)__cvta_generic_to_shared(smem);

    const int b = blockIdx.y, m0 = blockIdx.x << 6;
    const int tid = threadIdx.x, wid = tid >> 5, lane = tid & 31;
    const int dw = wid & 3, mw = wid >> 2;

    float CK[4][4] = {}, CV[4][4] = {};

    auto issue = [&](int cc, int t) {
        int c0 = cc << 6;
        for (int i = tid; i < 512; i += 256) {
            int r = i >> 3, pos = i & 7;
            uint32_t dst = t * 8192 + r * 128 + ((pos ^ (r & 7)) << 4);
            cp16(s_u + dst,
                 g_x2ph + ((size_t)(b * C2 + c0 + r) << 10) + m0 + (pos << 3));
            cp16(s_u + 16384 + dst, g_Wkh + r * C2 + c0 + (pos << 3));
            cp16(s_u + 32768 + dst, g_Wvh + r * C2 + c0 + (pos << 3));
        }
        cp_commit();
    };

    issue(0, 0);
    for (int cc = 0; cc < 8; cc++) {
        int cur = cc & 1;
        cp_wait0();
        __syncthreads();
        if (cc < 7) issue(cc + 1, cur ^ 1);

        uint32_t sX_u = s_u + cur * 8192;
        uint32_t sWk_u = s_u + 16384 + cur * 8192;
        uint32_t sWv_u = s_u + 32768 + cur * 8192;
#pragma unroll
        for (int ks = 0; ks < 4; ks++) {
            int ar = (dw << 4) + (lane & 15);
            int ag = (ks << 1) + (lane >> 4);
            uint32_t aoff = ar * 128 + ((ag ^ (ar & 7)) << 4);
            uint32_t Ak[4], Av[4];
            ldsm4(Ak[0], Ak[1], Ak[2], Ak[3], sWk_u + aoff);
            ldsm4(Av[0], Av[1], Av[2], Av[3], sWv_u + aoff);
            int krow = (ks << 4) + (lane & 7) + (((lane >> 3) & 1) << 3);
#pragma unroll
            for (int nt = 0; nt < 2; nt++) {
                int ncol = (mw << 5) + (nt << 4) + ((lane >> 4) << 3);
                uint32_t b0, b1, b2, b3;
                ldsm4t(b0, b1, b2, b3,
                       sX_u + krow * 128 + (((ncol >> 3) ^ (krow & 7)) << 4));
                mma16816(CK[2 * nt], Ak, b0, b1);
                mma16816(CK[2 * nt + 1], Ak, b2, b3);
                mma16816(CV[2 * nt], Av, b0, b1);
                mma16816(CV[2 * nt + 1], Av, b2, b3);
            }
        }
    }
    int row0 = (dw << 4) + (lane >> 2);
    float bk0 = bk[row0], bk1 = bk[row0 + 8];
    float bv0 = bv[row0], bv1 = bv[row0 + 8];
    __nv_bfloat16* Kp = g_Kth + ((size_t)b * 64 + row0) * M + m0;
    __nv_bfloat16* Vp = g_Vth + ((size_t)b * 64 + row0) * M + m0;
#pragma unroll
    for (int nt = 0; nt < 2; nt++)
#pragma unroll
        for (int h = 0; h < 2; h++) {
            int ci = 2 * nt + h;
            int ncol = (mw << 5) + (nt << 4) + (h << 3) + ((lane & 3) << 1);
            // K pre-scaled by log2e so attention uses raw ex2
            *(uint32_t*)(Kp + ncol) =
                pack_bf16((CK[ci][0] + bk0) * LOG2E, (CK[ci][1] + bk0) * LOG2E);
            *(uint32_t*)(Kp + (size_t)8 * M + ncol) =
                pack_bf16((CK[ci][2] + bk1) * LOG2E, (CK[ci][3] + bk1) * LOG2E);
            *(uint32_t*)(Vp + ncol) = pack_bf16(CV[ci][0] + bv0, CV[ci][1] + bv0);
            *(uint32_t*)(Vp + (size_t)8 * M + ncol) = pack_bf16(CV[ci][2] + bv1, CV[ci][3] + bv1);
        }
}

// ---------------- kernel C: Q projection, reg-prefetch double buffer ----------------
__global__ __launch_bounds__(256) void qproj_kernel(
        const float* __restrict__ x1, const float* __restrict__ bq) {
    __shared__ __align__(16) char smem[49152];  // sW[4][8K] + sX[2][8K]
    const uint32_t s_u = (uint32_t)__cvta_generic_to_shared(smem);
    const uint32_t sXb_u = s_u + 32768;

    const int b = blockIdx.y, n0 = blockIdx.x << 6;
    const int tid = threadIdx.x, wid = tid >> 5, lane = tid & 31;
    const int dw = wid & 3, mw = wid >> 2;

    for (int i = tid; i < 2048; i += 256) {
        int ch = i >> 9, j = i & 511, r = j >> 3, pos = j & 7;
        cp16(s_u + ch * 8192 + r * 128 + ((pos ^ (r & 7)) << 4),
             g_Wqh + r * C1 + (ch << 6) + (pos << 3));
    }
    cp_commit();

    const int r0 = tid >> 4, p4 = tid & 15;
    const float* xbase = x1 + ((size_t)(b * C1) << 12) + n0 + (p4 << 2);
    float4 f[4];
#pragma unroll
    for (int k = 0; k < 4; k++)
        f[k] = *(const float4*)(xbase + ((size_t)(r0 + 16 * k) << 12));

    float C[4][4] = {};
    const int r7 = r0 & 7;
    const uint32_t sphys = r0 * 128 + (((p4 >> 1) ^ r7) << 4) + ((p4 & 1) << 3);

    for (int cc = 0; cc < 4; cc++) {
        int cur = cc & 1;
        char* xb = smem + 32768 + cur * 8192;
#pragma unroll
        for (int k = 0; k < 4; k++)
            *(uint2*)(xb + sphys + k * 2048) =
                make_uint2(pack_bf16(f[k].x, f[k].y), pack_bf16(f[k].z, f[k].w));
        float4 f2[4];
        if (cc < 3) {
#pragma unroll
            for (int k = 0; k < 4; k++)
                f2[k] = *(const float4*)(xbase +
                         ((size_t)(((cc + 1) << 6) + r0 + 16 * k) << 12));
        }
        if (cc == 0) cp_wait0();
        __syncthreads();

        uint32_t sW_u = s_u + cc * 8192;
        uint32_t sX_u = sXb_u + cur * 8192;
#pragma unroll
        for (int ks = 0; ks < 4; ks++) {
            int ar = (dw << 4) + (lane & 15);
            int ag = (ks << 1) + (lane >> 4);
            uint32_t A[4];
            ldsm4(A[0], A[1], A[2], A[3], sW_u + ar * 128 + ((ag ^ (ar & 7)) << 4));
            int krow = (ks << 4) + (lane & 7) + (((lane >> 3) & 1) << 3);
#pragma unroll
            for (int nt = 0; nt < 2; nt++) {
                int ncol = (mw << 5) + (nt << 4) + ((lane >> 4) << 3);
                uint32_t b0, b1, b2, b3;
                ldsm4t(b0, b1, b2, b3,
                       sX_u + krow * 128 + (((ncol >> 3) ^ (krow & 7)) << 4));
                mma16816(C[2 * nt], A, b0, b1);
                mma16816(C[2 * nt + 1], A, b2, b3);
            }
        }
        if (cc < 3) {
#pragma unroll
            for (int k = 0; k < 4; k++) f[k] = f2[k];
        }
    }
    int row0 = (dw << 4) + (lane >> 2);
    float b0v = bq[row0], b1v = bq[row0 + 8];
    __nv_bfloat16* Qp = g_Qth + ((size_t)b * 64 + row0) * HW + n0;
#pragma unroll
    for (int nt = 0; nt < 2; nt++)
#pragma unroll
        for (int h = 0; h < 2; h++) {
            int ci = 2 * nt + h;
            int ncol = (mw << 5) + (nt << 4) + (h << 3) + ((lane & 3) << 1);
            *(uint32_t*)(Qp + ncol) = pack_bf16(C[ci][0] + b0v, C[ci][1] + b0v);
            *(uint32_t*)(Qp + (size_t)8 * HW + ncol) = pack_bf16(C[ci][2] + b1v, C[ci][3] + b1v);
        }
}

// ---------------- kernel D: attention + out-proj + residual ----------------
// CTA: 128 queries, 4 warps, warp = 32 queries (two m16 fragments share B frags).
__global__ __launch_bounds__(128, 2) void attn_kernel(
        const float* __restrict__ x1, const float* __restrict__ bo,
        float* __restrict__ out) {
    extern __shared__ char sm[];
    float* sY = (float*)(sm + 32768);

    const int b = blockIdx.y, n0 = blockIdx.x << 7;
    const int tid = threadIdx.x, wid = tid >> 5, lane = tid & 31;
    const uint32_t sm_u = (uint32_t)__cvta_generic_to_shared(sm);

    const __nv_bfloat16* Qg = g_Qth + (size_t)b * 64 * HW + n0;
    const __nv_bfloat16* Kg0 = g_Kth + (size_t)b * 64 * M;
    const __nv_bfloat16* Vg0 = g_Vth + (size_t)b * 64 * M;

    // stage Qt [64][128] into sm[0,16K) + K/V tile 0 into B1
    for (int i = tid; i < 1024; i += 128) {
        int r = i >> 4, pos = i & 15;
        cp16(sm_u + r * 256 + ((pos ^ (r & 7)) << 4), Qg + (size_t)r * HW + (pos << 3));
    }
    for (int i = tid; i < 512; i += 128) {
        int r = i >> 3, pos = i & 7;
        uint32_t sw = ((pos ^ (r & 7)) << 4);
        cp16(sm_u + 16384 + r * 128 + sw, Kg0 + (size_t)r * M + (pos << 3));
        cp16(sm_u + 24576 + r * 128 + sw, Vg0 + (size_t)r * M + (pos << 3));
    }
    cp_commit(); cp_wait0();
    __syncthreads();

    // Q fragments: two m16 blocks per warp, 4 k-steps each
    uint32_t Qf[2][4][4];
#pragma unroll
    for (int h = 0; h < 2; h++) {
        int mcol = (wid << 5) + (h << 4) + (((lane >> 3) & 1) << 3);
#pragma unroll
        for (int s = 0; s < 4; s++) {
            int krow = (s << 4) + (lane & 7) + ((lane >> 4) << 3);
            ldsm4t(Qf[h][s][0], Qf[h][s][1], Qf[h][s][2], Qf[h][s][3],
                   sm_u + krow * 256 + (((mcol >> 3) ^ (krow & 7)) << 4));
        }
    }
    __syncthreads();   // sm[0,16K) -> buffer B0

    float O[2][8][4] = {};
    float l0[2] = {}, l1[2] = {};

    const int brow = (lane & 7) + ((lane >> 4) << 3);
    const int bgsel = (lane >> 3) & 1;
    const int tkrow = (lane & 7) + (((lane >> 3) & 1) << 3);
    const int tnsel = (lane >> 4) << 3;

    for (int kt = 0; kt < 16; kt++) {
        uint32_t cbase = sm_u + (((kt & 1) ^ 1) << 14);
        if (kt < 15) {
            uint32_t pb = sm_u + ((kt & 1) << 14);
            const __nv_bfloat16* Kg = Kg0 + (kt + 1) * 64;
            const __nv_bfloat16* Vg = Vg0 + (kt + 1) * 64;
            for (int i = tid; i < 512; i += 128) {
                int r = i >> 3, pos = i & 7;
                uint32_t sw = ((pos ^ (r & 7)) << 4);
                cp16(pb + r * 128 + sw, Kg + (size_t)r * M + (pos << 3));
                cp16(pb + 8192 + r * 128 + sw, Vg + (size_t)r * M + (pos << 3));
            }
        } else {
            // kt==15 computes on B0; B1 free -> Wo rows 128..255
            for (int i = tid; i < 1024; i += 128) {
                int r = 128 + (i >> 3), pos = i & 7;
                cp16(sm_u + r * 128 + ((pos ^ (r & 7)) << 4), g_Woh + r * 64 + (pos << 3));
            }
        }
        cp_commit();

        // S = Q K^T  (each K fragment feeds both m16 blocks)
        float S[2][8][4] = {};
#pragma unroll
        for (int s = 0; s < 4; s++) {
            int krow = (s << 4) + tkrow;
            uint32_t rb = cbase + krow * 128;
            int r7x = (krow & 7);
#pragma unroll
            for (int nh = 0; nh < 4; nh++) {
                int ncol = (nh << 4) + tnsel;
                uint32_t b0, b1, b2, b3;
                ldsm4t(b0, b1, b2, b3, rb + (((ncol >> 3) ^ r7x) << 4));
#pragma unroll
                for (int h = 0; h < 2; h++) {
                    mma16816(S[h][2 * nh], Qf[h][s], b0, b1);
                    mma16816(S[h][2 * nh + 1], Qf[h][s], b2, b3);
                }
            }
        }
        // softmax numerator + pack
        uint32_t Pf[2][4][4];
#pragma unroll
        for (int h = 0; h < 2; h++) {
#pragma unroll
            for (int nt = 0; nt < 8; nt++) {
#pragma unroll
                for (int j = 0; j < 4; j++) S[h][nt][j] = ex2f(S[h][nt][j]);
                l0[h] += S[h][nt][0] + S[h][nt][1];
                l1[h] += S[h][nt][2] + S[h][nt][3];
            }
#pragma unroll
            for (int kk = 0; kk < 4; kk++) {
                Pf[h][kk][0] = pack_bf16(S[h][2 * kk][0], S[h][2 * kk][1]);
                Pf[h][kk][1] = pack_bf16(S[h][2 * kk][2], S[h][2 * kk][3]);
                Pf[h][kk][2] = pack_bf16(S[h][2 * kk + 1][0], S[h][2 * kk + 1][1]);
                Pf[h][kk][3] = pack_bf16(S[h][2 * kk + 1][2], S[h][2 * kk + 1][3]);
            }
        }
        // O += P V
        uint32_t vbase = cbase + 8192;
#pragma unroll
        for (int kk = 0; kk < 4; kk++) {
#pragma unroll
            for (int dh = 0; dh < 4; dh++) {
                int r = (dh << 4) + brow;
                int g = (kk << 1) + bgsel;
                uint32_t b0, b1, b2, b3;
                ldsm4(b0, b1, b2, b3, vbase + r * 128 + ((g ^ (r & 7)) << 4));
#pragma unroll
                for (int h = 0; h < 2; h++) {
                    mma16816(O[h][2 * dh], Pf[h][kk], b0, b1);
                    mma16816(O[h][2 * dh + 1], Pf[h][kk], b2, b3);
                }
            }
        }
        cp_wait0();
        __syncthreads();
    }

    // normalize, build O fragments
    uint32_t Of[2][4][4];
#pragma unroll
    for (int h = 0; h < 2; h++) {
        float a0 = l0[h], a1 = l1[h];
        a0 += __shfl_xor_sync(0xffffffffu, a0, 1);
        a0 += __shfl_xor_sync(0xffffffffu, a0, 2);
        a1 += __shfl_xor_sync(0xffffffffu, a1, 1);
        a1 += __shfl_xor_sync(0xffffffffu, a1, 2);
        float inv0 = 1.0f / a0, inv1 = 1.0f / a1;
#pragma unroll
        for (int s = 0; s < 4; s++) {
            Of[h][s][0] = pack_bf16(O[h][2 * s][0] * inv0, O[h][2 * s][1] * inv0);
            Of[h][s][1] = pack_bf16(O[h][2 * s][2] * inv1, O[h][2 * s][3] * inv1);
            Of[h][s][2] = pack_bf16(O[h][2 * s + 1][0] * inv0, O[h][2 * s + 1][1] * inv0);
            Of[h][s][3] = pack_bf16(O[h][2 * s + 1][2] * inv1, O[h][2 * s + 1][3] * inv1);
        }
    }

    // stage Wo rows 0..127 into B0 (upper half already in B1)
    for (int i = tid; i < 1024; i += 128) {
        int r = i >> 3, pos = i & 7;
        cp16(sm_u + r * 128 + ((pos ^ (r & 7)) << 4), g_Woh + r * 64 + (pos << 3));
    }
    cp_commit(); cp_wait0();
    __syncthreads();

    const size_t xoff = (size_t)b * (C1 * HW) + n0;
    for (int cc = 0; cc < 4; cc++) {
        float Y[2][8][4] = {};
#pragma unroll
        for (int s = 0; s < 4; s++) {
#pragma unroll
            for (int ch = 0; ch < 4; ch++) {
                int r = (cc << 6) + (ch << 4) + brow;
                int g = (s << 1) + bgsel;
                uint32_t b0, b1, b2, b3;
                ldsm4(b0, b1, b2, b3, sm_u + r * 128 + ((g ^ (r & 7)) << 4));
#pragma unroll
                for (int h = 0; h < 2; h++) {
                    mma16816(Y[h][2 * ch], Of[h][s], b0, b1);
                    mma16816(Y[h][2 * ch + 1], Of[h][s], b2, b3);
                }
            }
        }
        if (cc) __syncthreads();
#pragma unroll
        for (int h = 0; h < 2; h++) {
            int qrow = (wid << 5) + (h << 4) + (lane >> 2);
#pragma unroll
            for (int nt = 0; nt < 8; nt++) {
                int c = (nt << 3) + ((lane & 3) << 1);
                sY[c * LDY + qrow] = Y[h][nt][0];
                sY[(c + 1) * LDY + qrow] = Y[h][nt][1];
                sY[c * LDY + qrow + 8] = Y[h][nt][2];
                sY[(c + 1) * LDY + qrow + 8] = Y[h][nt][3];
            }
        }
        __syncthreads();
        // residual + bias, float4 vectorized
        for (int i2 = tid; i2 < 2048; i2 += 128) {
            int c = i2 >> 5, q4 = (i2 & 31) << 2;
            size_t gaddr = xoff + (size_t)((cc << 6) + c) * HW + q4;
            float4 xv = *(const float4*)(x1 + gaddr);
            float4 yv = *(const float4*)&sY[c * LDY + q4];
            float bb = bo[(cc << 6) + c];
            float4 o;
            o.x = xv.x + yv.x + bb;
            o.y = xv.y + yv.y + bb;
            o.z = xv.z + yv.z + bb;
            o.w = xv.w + yv.w + bb;
            *(float4*)(out + gaddr) = o;
        }
    }
}

extern "C" void kernel_launch(void* const* d_in, const int* in_sizes, int n_in,
                              void* d_out, int out_size) {
    const float* x1 = (const float*)d_in[0];
    const float* x2 = (const float*)d_in[1];
    const float* Wq = (const float*)d_in[2];
    const float* bq = (const float*)d_in[3];
    const float* Wk = (const float*)d_in[4];
    const float* bk = (const float*)d_in[5];
    const float* Wv = (const float*)d_in[6];
    const float* bv = (const float*)d_in[7];
    const float* Wo = (const float*)d_in[8];
    const float* bo = (const float*)d_in[9];
    float* out = (float*)d_out;
    (void)in_sizes; (void)n_in; (void)out_size;

    static const int smem_attn = 32768 + 64 * LDY * 4;
    cudaFuncSetAttribute(attn_kernel, cudaFuncAttributeMaxDynamicSharedMemorySize,
                         smem_attn);

    prep_kernel<<<8192 + 384, 256>>>(x2, Wk, Wv, Wq, Wo);
    kvproj_kernel<<<dim3(M / 64, NB), 256>>>(bk, bv);
    qproj_kernel<<<dim3(HW / 64, NB), 256>>>(x1, bq);
    attn_kernel<<<dim3(HW / 128, NB), 128, smem_attn>>>(x1, bo, out);
}